// round 3
// baseline (speedup 1.0000x reference)
#include <cuda_runtime.h>
#include <math.h>

// Problem constants
#define T_SEQ 2048
#define BATCH 2
#define DMODEL 1024
#define HEADS 16
#define NWAVE 64
#define HDIM 64
#define ROWS (BATCH * T_SEQ)            // 4096
#define SLICE ((size_t)ROWS * DMODEL)   // 4194304 elements
#define BH (BATCH * HEADS)              // 32
#define CHUNK 64
#define NCHUNK (T_SEQ / CHUNK)          // 32

// ---------------- device scratch (no allocations allowed) ----------------
__device__ float g_wave[4 * SLICE];              // qf, kf, qp, kp raw projections
__device__ float g_v[SLICE];                     // v projection [b,t,h*64+d]
__device__ float g_qn[(size_t)BH * T_SEQ * NWAVE];  // normalized q waves [bh][t][w]
__device__ float g_kn[(size_t)BH * T_SEQ * NWAVE];  // normalized k waves [bh][t][w]
__device__ float g_M[(size_t)BH * NCHUNK * NWAVE * HDIM];  // per-chunk kn^T v
__device__ float g_S[(size_t)BH * NCHUNK * NWAVE * HDIM];  // exclusive prefix states
__device__ float g_ao[SLICE];                    // attention output [b,t,h*64+d]

// ---------------- packed f32x2 helpers (Blackwell FFMA2) ----------------
__device__ __forceinline__ void ffma2(unsigned long long& d,
                                      unsigned long long a,
                                      unsigned long long b)
{
    asm("fma.rn.f32x2 %0, %1, %2, %0;" : "+l"(d) : "l"(a), "l"(b));
}
__device__ __forceinline__ unsigned long long pack2(float x)
{
    unsigned long long r;
    asm("mov.b64 %0, {%1, %1};" : "=l"(r) : "f"(x));
    return r;
}
__device__ __forceinline__ float2 unpack2(unsigned long long v)
{
    float2 r;
    asm("mov.b64 {%0, %1}, %2;" : "=f"(r.x), "=f"(r.y) : "l"(v));
    return r;
}

// ---------------- 128x128 FFMA2 register-tiled SGEMM (C = A*B + bias) ----------------
// A [M,K] row-major, B [K,N] row-major. 256 threads.
// Thread tile: 4 rows x 16 cols; cols are 4 groups of 4 at stride 32
// (conflict-free LDS.128 from Bs). K tile = 16 with register prefetch.
__device__ __forceinline__ void sgemm128(const float* __restrict__ A,
                                         const float* __restrict__ Bw,
                                         const float* __restrict__ bias,
                                         float* __restrict__ C,
                                         int N, int K)
{
    __shared__ float As[16][128];   // As[k][m]
    __shared__ float Bs[16][128];   // Bs[k][n]
    const int tid  = threadIdx.x;
    const int row0 = blockIdx.y * 128;
    const int col0 = blockIdx.x * 128;
    const int arow = tid >> 1, acol = (tid & 1) * 8;     // A tile: 128 rows x 16 k
    const int brow = tid >> 4, bcol = (tid & 15) * 4;    // B tile: 16 k x 128 n
    const int ty = tid >> 3;        // 0..31 -> 4 rows each
    const int tx = tid & 7;         // 0..7  -> 4 col-groups of 4, stride 32

    unsigned long long acc[4][8];   // [row][col-pair]; pair jj: group jj>>1, sub (jj&1)*2
#pragma unroll
    for (int i = 0; i < 4; i++)
#pragma unroll
        for (int j = 0; j < 8; j++) acc[i][j] = 0ULL;

    const float* aptr = A + (size_t)(row0 + arow) * K + acol;
    const float* bptr = Bw + (size_t)brow * N + col0 + bcol;

    float4 pa0 = *(const float4*)(aptr);
    float4 pa1 = *(const float4*)(aptr + 4);
    float4 pb0 = *(const float4*)(bptr);
    float4 pb1 = *(const float4*)(bptr + 64);

    for (int kk = 0; kk < K; kk += 16) {
        // store current tile to shared
        As[acol + 0][arow] = pa0.x;
        As[acol + 1][arow] = pa0.y;
        As[acol + 2][arow] = pa0.z;
        As[acol + 3][arow] = pa0.w;
        As[acol + 4][arow] = pa1.x;
        As[acol + 5][arow] = pa1.y;
        As[acol + 6][arow] = pa1.z;
        As[acol + 7][arow] = pa1.w;
        *(float4*)(&Bs[brow][bcol])      = pb0;
        *(float4*)(&Bs[brow][bcol + 64]) = pb1;
        __syncthreads();

        // prefetch next tile while computing
        if (kk + 16 < K) {
            pa0 = *(const float4*)(aptr + kk + 16);
            pa1 = *(const float4*)(aptr + kk + 20);
            const float* bn = bptr + (size_t)(kk + 16) * N;
            pb0 = *(const float4*)(bn);
            pb1 = *(const float4*)(bn + 64);
        }

#pragma unroll
        for (int k = 0; k < 16; k++) {
            float4 av = *(const float4*)(&As[k][ty * 4]);
            unsigned long long ap2[4];
            ap2[0] = pack2(av.x);
            ap2[1] = pack2(av.y);
            ap2[2] = pack2(av.z);
            ap2[3] = pack2(av.w);
            ulonglong2 b0 = *(const ulonglong2*)(&Bs[k][tx * 4]);
            ulonglong2 b1 = *(const ulonglong2*)(&Bs[k][tx * 4 + 32]);
            ulonglong2 b2 = *(const ulonglong2*)(&Bs[k][tx * 4 + 64]);
            ulonglong2 b3 = *(const ulonglong2*)(&Bs[k][tx * 4 + 96]);
            unsigned long long bv[8] = {b0.x, b0.y, b1.x, b1.y,
                                        b2.x, b2.y, b3.x, b3.y};
#pragma unroll
            for (int i = 0; i < 4; i++)
#pragma unroll
                for (int j = 0; j < 8; j++)
                    ffma2(acc[i][j], ap2[i], bv[j]);
        }
        __syncthreads();
    }

    // epilogue: unpack, add bias, store
#pragma unroll
    for (int i = 0; i < 4; i++) {
        int r = row0 + ty * 4 + i;
#pragma unroll
        for (int q = 0; q < 4; q++) {
            int c = col0 + q * 32 + tx * 4;
            float2 lo = unpack2(acc[i][2 * q]);
            float2 hi = unpack2(acc[i][2 * q + 1]);
            float4 bb = *(const float4*)(bias + c);
            float4 o;
            o.x = lo.x + bb.x;
            o.y = lo.y + bb.y;
            o.z = hi.x + bb.z;
            o.w = hi.y + bb.w;
            *(float4*)(C + (size_t)r * N + c) = o;
        }
    }
}

// ---------------- projection kernel: 5 GEMMs via blockIdx.z ----------------
__global__ __launch_bounds__(256) void proj_kernel(
    const float* __restrict__ x,
    const float* __restrict__ Wqf, const float* __restrict__ bqf,
    const float* __restrict__ Wkf, const float* __restrict__ bkf,
    const float* __restrict__ Wqp, const float* __restrict__ bqp,
    const float* __restrict__ Wkp, const float* __restrict__ bkp,
    const float* __restrict__ Wv,  const float* __restrict__ bv)
{
    const float* W;
    const float* b;
    float* C;
    switch (blockIdx.z) {
        case 0: W = Wqf; b = bqf; C = g_wave;             break;
        case 1: W = Wkf; b = bkf; C = g_wave + SLICE;     break;
        case 2: W = Wqp; b = bqp; C = g_wave + 2 * SLICE; break;
        case 3: W = Wkp; b = bkp; C = g_wave + 3 * SLICE; break;
        default: W = Wv; b = bv;  C = g_v;                break;
    }
    sgemm128(x, W, b, C, DMODEL, DMODEL);
}

// ---------------- final output GEMM: d_out = g_ao @ Wo + bo ----------------
__global__ __launch_bounds__(256) void out_gemm_kernel(const float* __restrict__ Wo,
                                                       const float* __restrict__ bo,
                                                       float* __restrict__ out)
{
    sgemm128(g_ao, Wo, bo, out, DMODEL, DMODEL);
}

// ---------------- wave normalization: w = sin(f*t + p); w /= max(||w||, eps) ----------------
// One warp per (qk, b, t, h) row; 2 elements per lane.
__global__ __launch_bounds__(256) void wave_kernel()
{
    int gid  = blockIdx.x * 8 + (threadIdx.x >> 5);   // 0 .. 131071
    int lane = threadIdx.x & 31;
    int qk = gid >> 16;          // 0 = q, 1 = k
    int r  = gid & 0xFFFF;       // b*T*H + t*H + h
    int h = r & 15;
    int t = (r >> 4) & 2047;
    int b = r >> 15;

    const float* fb = g_wave + (size_t)qk * SLICE;        // qf or kf
    const float* pb = g_wave + (size_t)(2 + qk) * SLICE;  // qp or kp
    size_t base = ((size_t)(b * T_SEQ + t)) * DMODEL + h * NWAVE;
    float tf = (float)t;

    float f0 = fb[base + lane],      f1 = fb[base + lane + 32];
    float p0 = pb[base + lane],      p1 = pb[base + lane + 32];
    // match JAX: round(f*t) then round(+p) — forbid FMA contraction here
    float w0 = sinf(__fadd_rn(__fmul_rn(f0, tf), p0));
    float w1 = sinf(__fadd_rn(__fmul_rn(f1, tf), p1));

    float s = w0 * w0 + w1 * w1;
#pragma unroll
    for (int o = 16; o > 0; o >>= 1) s += __shfl_xor_sync(0xffffffffu, s, o);
    float inv = 1.f / fmaxf(sqrtf(s), 1e-12f);

    float* dst = qk ? g_kn : g_qn;
    size_t ob = ((size_t)((b * HEADS + h) * T_SEQ + t)) * NWAVE;
    dst[ob + lane]      = w0 * inv;
    dst[ob + lane + 32] = w1 * inv;
}

// ---------------- pass 1: per-chunk KV sums M_c = kn_c^T @ v_c  (64x64, K=64) ----------------
__global__ __launch_bounds__(256) void kvchunk_kernel()
{
    int c = blockIdx.x, bh = blockIdx.y;
    int b = bh >> 4, h = bh & 15;
    __shared__ float ks[CHUNK * NWAVE];
    __shared__ float vs[CHUNK * HDIM];
    const float* knp = g_kn + ((size_t)bh * T_SEQ + c * CHUNK) * NWAVE;
    const float* vp  = g_v + ((size_t)(b * T_SEQ + c * CHUNK)) * DMODEL + h * HDIM;
    for (int idx = threadIdx.x; idx < CHUNK * NWAVE; idx += 256) {
        ks[idx] = knp[idx];                       // [s][w]
        int s = idx >> 6, d = idx & 63;
        vs[idx] = vp[(size_t)s * DMODEL + d];     // [s][d]
    }
    __syncthreads();
    int tw = (threadIdx.x >> 4) * 4, td = (threadIdx.x & 15) * 4;
    float acc[4][4] = {};
    for (int s = 0; s < CHUNK; s++) {
        float kr[4], vr[4];
#pragma unroll
        for (int i = 0; i < 4; i++) kr[i] = ks[s * NWAVE + tw + i];
#pragma unroll
        for (int j = 0; j < 4; j++) vr[j] = vs[s * HDIM + td + j];
#pragma unroll
        for (int i = 0; i < 4; i++)
#pragma unroll
            for (int j = 0; j < 4; j++)
                acc[i][j] = fmaf(kr[i], vr[j], acc[i][j]);
    }
    float* Mp = g_M + ((size_t)bh * NCHUNK + c) * (NWAVE * HDIM);
#pragma unroll
    for (int i = 0; i < 4; i++)
#pragma unroll
        for (int j = 0; j < 4; j++)
            Mp[(tw + i) * HDIM + td + j] = acc[i][j];
}

// ---------------- pass 2: exclusive prefix sum over chunks per (bh, element) ----------------
__global__ __launch_bounds__(256) void prefix_kernel()
{
    int bh = blockIdx.y;
    int e = blockIdx.x * 256 + threadIdx.x;   // 0..4095
    size_t base = (size_t)bh * NCHUNK * (NWAVE * HDIM) + e;
    float run = 0.f;
#pragma unroll
    for (int c = 0; c < NCHUNK; c++) {
        g_S[base + (size_t)c * (NWAVE * HDIM)] = run;
        run += g_M[base + (size_t)c * (NWAVE * HDIM)];
    }
}

// ---------------- pass 3: per-chunk output ----------------
// out_c = (causal(qn_c @ kn_c^T) @ v_c + qn_c @ S_c) * scale[h] / sqrt(t+1)
__global__ __launch_bounds__(256) void attnout_kernel(const float* __restrict__ scale)
{
    int c = blockIdx.x, bh = blockIdx.y;
    int b = bh >> 4, h = bh & 15;
    int t0 = c * CHUNK;
    __shared__ float Xs[NWAVE * CHUNK];   // qT: [w][t]
    __shared__ float Ys[NWAVE * CHUNK];   // kT, then v, then S
    __shared__ float Zs[CHUNK * CHUNK];   // intra-chunk attn [t][s]

    const float* qp_ = g_qn + ((size_t)bh * T_SEQ + t0) * NWAVE;
    const float* kp_ = g_kn + ((size_t)bh * T_SEQ + t0) * NWAVE;
    for (int idx = threadIdx.x; idx < CHUNK * NWAVE; idx += 256) {
        int t = idx >> 6, w = idx & 63;
        Xs[w * CHUNK + t] = qp_[idx];
        Ys[w * CHUNK + t] = kp_[idx];
    }
    __syncthreads();

    int ty = threadIdx.x >> 4, tx = threadIdx.x & 15;
    int tr = ty * 4, sc = tx * 4;

    // intra-chunk attn = qn @ kn^T with causal mask (local s <= local t)
    {
        float acc[4][4] = {};
        for (int w = 0; w < NWAVE; w++) {
            float qr[4], kr[4];
#pragma unroll
            for (int i = 0; i < 4; i++) qr[i] = Xs[w * CHUNK + tr + i];
#pragma unroll
            for (int j = 0; j < 4; j++) kr[j] = Ys[w * CHUNK + sc + j];
#pragma unroll
            for (int i = 0; i < 4; i++)
#pragma unroll
                for (int j = 0; j < 4; j++)
                    acc[i][j] = fmaf(qr[i], kr[j], acc[i][j]);
        }
#pragma unroll
        for (int i = 0; i < 4; i++)
#pragma unroll
            for (int j = 0; j < 4; j++)
                Zs[(tr + i) * CHUNK + sc + j] = (sc + j <= tr + i) ? acc[i][j] : 0.f;
    }
    __syncthreads();

    // load v chunk into Ys
    const float* vp = g_v + ((size_t)(b * T_SEQ + t0)) * DMODEL + h * HDIM;
    for (int idx = threadIdx.x; idx < CHUNK * HDIM; idx += 256) {
        int s = idx >> 6, d = idx & 63;
        Ys[idx] = vp[(size_t)s * DMODEL + d];
    }
    __syncthreads();

    float out[4][4] = {};
    // intra-chunk: attn @ v
    for (int s = 0; s < CHUNK; s++) {
        float ar[4], vr[4];
#pragma unroll
        for (int i = 0; i < 4; i++) ar[i] = Zs[(tr + i) * CHUNK + s];
#pragma unroll
        for (int j = 0; j < 4; j++) vr[j] = Ys[s * HDIM + sc + j];
#pragma unroll
        for (int i = 0; i < 4; i++)
#pragma unroll
            for (int j = 0; j < 4; j++)
                out[i][j] = fmaf(ar[i], vr[j], out[i][j]);
    }
    __syncthreads();

    // load prefix state S into Ys
    const float* Sp = g_S + ((size_t)bh * NCHUNK + c) * (NWAVE * HDIM);
    for (int idx = threadIdx.x; idx < NWAVE * HDIM; idx += 256) Ys[idx] = Sp[idx];
    __syncthreads();

    // cross-chunk: qn @ S
    for (int w = 0; w < NWAVE; w++) {
        float qr[4], sr[4];
#pragma unroll
        for (int i = 0; i < 4; i++) qr[i] = Xs[w * CHUNK + tr + i];
#pragma unroll
        for (int j = 0; j < 4; j++) sr[j] = Ys[w * HDIM + sc + j];
#pragma unroll
        for (int i = 0; i < 4; i++)
#pragma unroll
            for (int j = 0; j < 4; j++)
                out[i][j] = fmaf(qr[i], sr[j], out[i][j]);
    }

    float sch = scale[h];
    float* op = g_ao + ((size_t)(b * T_SEQ + t0)) * DMODEL + h * HDIM;
#pragma unroll
    for (int i = 0; i < 4; i++) {
        float fac = sch / sqrtf((float)(t0 + tr + i + 1));
        float4 o;
        o.x = out[i][0] * fac;
        o.y = out[i][1] * fac;
        o.z = out[i][2] * fac;
        o.w = out[i][3] * fac;
        *(float4*)(op + (size_t)(tr + i) * DMODEL + sc) = o;
    }
}

// ---------------- launch ----------------
extern "C" void kernel_launch(void* const* d_in, const int* in_sizes, int n_in,
                              void* d_out, int out_size)
{
    const float* x   = (const float*)d_in[0];
    const float* Wqf = (const float*)d_in[1];
    const float* bqf = (const float*)d_in[2];
    const float* Wkf = (const float*)d_in[3];
    const float* bkf = (const float*)d_in[4];
    const float* Wqp = (const float*)d_in[5];
    const float* bqp = (const float*)d_in[6];
    const float* Wkp = (const float*)d_in[7];
    const float* bkp = (const float*)d_in[8];
    const float* Wv  = (const float*)d_in[9];
    const float* bv  = (const float*)d_in[10];
    const float* Wo  = (const float*)d_in[11];
    const float* bo  = (const float*)d_in[12];
    const float* scl = (const float*)d_in[13];

    proj_kernel<<<dim3(DMODEL / 128, ROWS / 128, 5), 256>>>(
        x, Wqf, bqf, Wkf, bkf, Wqp, bqp, Wkp, bkp, Wv, bv);
    wave_kernel<<<(2 * BATCH * T_SEQ * HEADS) / 8, 256>>>();
    kvchunk_kernel<<<dim3(NCHUNK, BH), 256>>>();
    prefix_kernel<<<dim3(16, BH), 256>>>();
    attnout_kernel<<<dim3(NCHUNK, BH), 256>>>(scl);
    out_gemm_kernel<<<dim3(DMODEL / 128, ROWS / 128), 256>>>(Wo, bo, (float*)d_out);
}

// round 13
// speedup vs baseline: 1.1943x; 1.1943x over previous
#include <cuda_runtime.h>
#include <cuda_bf16.h>
#include <cstdint>
#include <math.h>

// Problem constants
#define T_SEQ 2048
#define BATCH 2
#define DMODEL 1024
#define HEADS 16
#define NWAVE 64
#define HDIM 64
#define ROWS (BATCH * T_SEQ)            // 4096
#define SLICE ((size_t)ROWS * DMODEL)   // 4194304 elements
#define BH (BATCH * HEADS)              // 32
#define CHUNK 64
#define NCHUNK (T_SEQ / CHUNK)          // 32

#define BK 32
#define STRIDE 40                        // bf16 elems per smem row (conflict-free)
#define ASZ (128 * STRIDE)               // elems per smem array (5120)
#define GEMM_DSMEM (2 * 4 * ASZ * 2)     // 81920 B

// ---------------- device scratch (no allocations allowed) ----------------
__device__ float g_wave[4 * SLICE];              // qf, kf, qp, kp raw projections
__device__ float g_v[SLICE];                     // v projection [b,t,h*64+d]
__device__ float g_qn[(size_t)BH * T_SEQ * NWAVE];
__device__ float g_kn[(size_t)BH * T_SEQ * NWAVE];
__device__ float g_M[(size_t)BH * NCHUNK * NWAVE * HDIM];
__device__ float g_S[(size_t)BH * NCHUNK * NWAVE * HDIM];
__device__ float g_ao[SLICE];                    // attention output

// 2-plane bf16 splits for HMMA GEMMs (qp, kp, v, out)
__device__ __nv_bfloat16 g_xh[SLICE], g_xl[SLICE];              // x hi/lo
__device__ __nv_bfloat16 g_wt2h[4u * 1024 * 1024];              // W^T hi: qp,kp,v,o
__device__ __nv_bfloat16 g_wt2l[4u * 1024 * 1024];              // W^T lo
__device__ __nv_bfloat16 g_aoh[SLICE], g_aol[SLICE];            // ao hi/lo

// ==================== packed f32x2 helpers (round-3 proven) ====================
__device__ __forceinline__ void ffma2(unsigned long long& d,
                                      unsigned long long a,
                                      unsigned long long b)
{
    asm("fma.rn.f32x2 %0, %1, %2, %0;" : "+l"(d) : "l"(a), "l"(b));
}
__device__ __forceinline__ unsigned long long pack2(float x)
{
    unsigned long long r;
    asm("mov.b64 %0, {%1, %1};" : "=l"(r) : "f"(x));
    return r;
}
__device__ __forceinline__ float2 unpack2(unsigned long long v)
{
    float2 r;
    asm("mov.b64 {%0, %1}, %2;" : "=f"(r.x), "=f"(r.y) : "l"(v));
    return r;
}

// ---------------- fp32 FFMA2 128x128 SGEMM (round-3 verbatim; PASSED) ----------------
// A [M,K] row-major, B [K,N] row-major. 256 threads.
__device__ __forceinline__ void sgemm128(const float* __restrict__ A,
                                         const float* __restrict__ Bw,
                                         const float* __restrict__ bias,
                                         float* __restrict__ C,
                                         int N, int K)
{
    __shared__ float As[16][128];
    __shared__ float Bs[16][128];
    const int tid  = threadIdx.x;
    const int row0 = blockIdx.y * 128;
    const int col0 = blockIdx.x * 128;
    const int arow = tid >> 1, acol = (tid & 1) * 8;
    const int brow = tid >> 4, bcol = (tid & 15) * 4;
    const int ty = tid >> 3;
    const int tx = tid & 7;

    unsigned long long acc[4][8];
#pragma unroll
    for (int i = 0; i < 4; i++)
#pragma unroll
        for (int j = 0; j < 8; j++) acc[i][j] = 0ULL;

    const float* aptr = A + (size_t)(row0 + arow) * K + acol;
    const float* bptr = Bw + (size_t)brow * N + col0 + bcol;

    float4 pa0 = *(const float4*)(aptr);
    float4 pa1 = *(const float4*)(aptr + 4);
    float4 pb0 = *(const float4*)(bptr);
    float4 pb1 = *(const float4*)(bptr + 64);

    for (int kk = 0; kk < K; kk += 16) {
        As[acol + 0][arow] = pa0.x;
        As[acol + 1][arow] = pa0.y;
        As[acol + 2][arow] = pa0.z;
        As[acol + 3][arow] = pa0.w;
        As[acol + 4][arow] = pa1.x;
        As[acol + 5][arow] = pa1.y;
        As[acol + 6][arow] = pa1.z;
        As[acol + 7][arow] = pa1.w;
        *(float4*)(&Bs[brow][bcol])      = pb0;
        *(float4*)(&Bs[brow][bcol + 64]) = pb1;
        __syncthreads();

        if (kk + 16 < K) {
            pa0 = *(const float4*)(aptr + kk + 16);
            pa1 = *(const float4*)(aptr + kk + 20);
            const float* bn = bptr + (size_t)(kk + 16) * N;
            pb0 = *(const float4*)(bn);
            pb1 = *(const float4*)(bn + 64);
        }

#pragma unroll
        for (int k = 0; k < 16; k++) {
            float4 av = *(const float4*)(&As[k][ty * 4]);
            unsigned long long ap2[4];
            ap2[0] = pack2(av.x);
            ap2[1] = pack2(av.y);
            ap2[2] = pack2(av.z);
            ap2[3] = pack2(av.w);
            ulonglong2 b0 = *(const ulonglong2*)(&Bs[k][tx * 4]);
            ulonglong2 b1 = *(const ulonglong2*)(&Bs[k][tx * 4 + 32]);
            ulonglong2 b2 = *(const ulonglong2*)(&Bs[k][tx * 4 + 64]);
            ulonglong2 b3 = *(const ulonglong2*)(&Bs[k][tx * 4 + 96]);
            unsigned long long bv[8] = {b0.x, b0.y, b1.x, b1.y,
                                        b2.x, b2.y, b3.x, b3.y};
#pragma unroll
            for (int i = 0; i < 4; i++)
#pragma unroll
                for (int j = 0; j < 8; j++)
                    ffma2(acc[i][j], ap2[i], bv[j]);
        }
        __syncthreads();
    }

#pragma unroll
    for (int i = 0; i < 4; i++) {
        int r = row0 + ty * 4 + i;
#pragma unroll
        for (int q = 0; q < 4; q++) {
            int c = col0 + q * 32 + tx * 4;
            float2 lo = unpack2(acc[i][2 * q]);
            float2 hi = unpack2(acc[i][2 * q + 1]);
            float4 bb = *(const float4*)(bias + c);
            float4 o;
            o.x = lo.x + bb.x;
            o.y = lo.y + bb.y;
            o.z = hi.x + bb.z;
            o.w = hi.y + bb.w;
            *(float4*)(C + (size_t)r * N + c) = o;
        }
    }
}

// fp32 frequency projections (precision-critical: feeds sin(f*t))
__global__ __launch_bounds__(256) void proj_f32(
    const float* __restrict__ x,
    const float* __restrict__ Wqf, const float* __restrict__ bqf,
    const float* __restrict__ Wkf, const float* __restrict__ bkf)
{
    int z = blockIdx.z;
    const float* W = z ? Wkf : Wqf;
    const float* b = z ? bkf : bqf;
    float* C = g_wave + (size_t)z * SLICE;
    sgemm128(x, W, b, C, DMODEL, DMODEL);
}

// ---------------- HMMA m16n8k16 bf16 -> fp32 ----------------
__device__ __forceinline__ void mma16816(float* d, const uint32_t* a, const uint32_t* b)
{
    asm volatile(
        "mma.sync.aligned.m16n8k16.row.col.f32.bf16.bf16.f32 "
        "{%0,%1,%2,%3}, {%4,%5,%6,%7}, {%8,%9}, {%0,%1,%2,%3};"
        : "+f"(d[0]), "+f"(d[1]), "+f"(d[2]), "+f"(d[3])
        : "r"(a[0]), "r"(a[1]), "r"(a[2]), "r"(a[3]), "r"(b[0]), "r"(b[1]));
}

// ==================== 2-plane split-bf16 HMMA GEMM core (round-11 verbatim) ====================
__device__ __forceinline__ void gemm_core(
    const __nv_bfloat16* __restrict__ Ah, const __nv_bfloat16* __restrict__ Al,
    const __nv_bfloat16* __restrict__ Bh, const __nv_bfloat16* __restrict__ Bl,
    const float* __restrict__ bias, float* __restrict__ C)
{
    extern __shared__ __nv_bfloat16 sm[];
    const int tid = threadIdx.x;
    const int wid = tid >> 5, lane = tid & 31;
    const int wr = wid >> 2, wc = wid & 3;
    const int g = lane >> 2, t = lane & 3;
    const int m0 = blockIdx.y * 128, n0 = blockIdx.x * 128;

    float acc[4][4][4];
#pragma unroll
    for (int mt = 0; mt < 4; mt++)
#pragma unroll
        for (int nt = 0; nt < 4; nt++)
#pragma unroll
            for (int i = 0; i < 4; i++) acc[mt][nt][i] = 0.f;

    const int lr = tid >> 1;
    const int lh = (tid & 1) * 16;
    const __nv_bfloat16* gAh = Ah + (size_t)(m0 + lr) * 1024 + lh;
    const __nv_bfloat16* gAl = Al + (size_t)(m0 + lr) * 1024 + lh;
    const __nv_bfloat16* gBh = Bh + (size_t)(n0 + lr) * 1024 + lh;
    const __nv_bfloat16* gBl = Bl + (size_t)(n0 + lr) * 1024 + lh;

    float4 r[8];
    auto ldg = [&](int st) {
        size_t o = (size_t)st * BK;
        r[0] = *(const float4*)(gAh + o); r[1] = *(const float4*)(gAh + o + 8);
        r[2] = *(const float4*)(gAl + o); r[3] = *(const float4*)(gAl + o + 8);
        r[4] = *(const float4*)(gBh + o); r[5] = *(const float4*)(gBh + o + 8);
        r[6] = *(const float4*)(gBl + o); r[7] = *(const float4*)(gBl + o + 8);
    };
    auto sts = [&](int b) {
        __nv_bfloat16* p = sm + (size_t)b * 4 * ASZ + lr * STRIDE + lh;
        *(float4*)(p)               = r[0]; *(float4*)(p + 8)           = r[1];
        *(float4*)(p + ASZ)         = r[2]; *(float4*)(p + ASZ + 8)     = r[3];
        *(float4*)(p + 2 * ASZ)     = r[4]; *(float4*)(p + 2 * ASZ + 8) = r[5];
        *(float4*)(p + 3 * ASZ)     = r[6]; *(float4*)(p + 3 * ASZ + 8) = r[7];
    };

    auto compute = [&](int b) {
        const __nv_bfloat16* base = sm + (size_t)b * 4 * ASZ;
        const __nv_bfloat16* pA = base + (wr * 64 + g) * STRIDE + 2 * t;
        const __nv_bfloat16* pB = base + 2 * ASZ + (wc * 32 + g) * STRIDE + 2 * t;
#pragma unroll
        for (int kk = 0; kk < 2; kk++) {
            uint32_t ah[4][4], al[4][4];
#pragma unroll
            for (int mt = 0; mt < 4; mt++) {
                const __nv_bfloat16* q = pA + mt * 16 * STRIDE + kk * 16;
                ah[mt][0] = *(const uint32_t*)(q);
                ah[mt][1] = *(const uint32_t*)(q + 8 * STRIDE);
                ah[mt][2] = *(const uint32_t*)(q + 8);
                ah[mt][3] = *(const uint32_t*)(q + 8 * STRIDE + 8);
                const __nv_bfloat16* ql = q + ASZ;
                al[mt][0] = *(const uint32_t*)(ql);
                al[mt][1] = *(const uint32_t*)(ql + 8 * STRIDE);
                al[mt][2] = *(const uint32_t*)(ql + 8);
                al[mt][3] = *(const uint32_t*)(ql + 8 * STRIDE + 8);
            }
#pragma unroll
            for (int nt = 0; nt < 4; nt++) {
                const __nv_bfloat16* q = pB + nt * 8 * STRIDE + kk * 16;
                uint32_t bh[2], bl[2];
                bh[0] = *(const uint32_t*)(q);
                bh[1] = *(const uint32_t*)(q + 8);
                bl[0] = *(const uint32_t*)(q + ASZ);
                bl[1] = *(const uint32_t*)(q + ASZ + 8);
#pragma unroll
                for (int mt = 0; mt < 4; mt++) {
                    mma16816(acc[mt][nt], ah[mt], bh);
                    mma16816(acc[mt][nt], ah[mt], bl);
                    mma16816(acc[mt][nt], al[mt], bh);
                }
            }
        }
    };

    ldg(0); sts(0);
    __syncthreads();
    for (int st = 0; st < 32; st++) {
        if (st + 1 < 32) ldg(st + 1);
        compute(st & 1);
        if (st + 1 < 32) {
            __syncthreads();
            sts((st + 1) & 1);
            __syncthreads();
        }
    }

#pragma unroll
    for (int mt = 0; mt < 4; mt++) {
#pragma unroll
        for (int nt = 0; nt < 4; nt++) {
            int row = m0 + wr * 64 + mt * 16 + g;
            int col = n0 + wc * 32 + nt * 8 + 2 * t;
            float2 bb = *(const float2*)(bias + col);
            float2 o0, o1;
            o0.x = acc[mt][nt][0] + bb.x;
            o0.y = acc[mt][nt][1] + bb.y;
            o1.x = acc[mt][nt][2] + bb.x;
            o1.y = acc[mt][nt][3] + bb.y;
            *(float2*)(C + (size_t)row * 1024 + col)       = o0;
            *(float2*)(C + (size_t)(row + 8) * 1024 + col) = o1;
        }
    }
}

// HMMA projections: qp (z=0), kp (z=1), v (z=2)
__global__ __launch_bounds__(256) void proj_hmma(
    const float* __restrict__ bqp, const float* __restrict__ bkp,
    const float* __restrict__ bv)
{
    int z = blockIdx.z;
    const float* bias = (z == 0) ? bqp : (z == 1) ? bkp : bv;
    float* C = (z == 0) ? g_wave + 2 * SLICE : (z == 1) ? g_wave + 3 * SLICE : g_v;
    gemm_core(g_xh, g_xl,
              g_wt2h + (size_t)z * 1048576, g_wt2l + (size_t)z * 1048576, bias, C);
}

__global__ __launch_bounds__(256) void out_tc(const float* __restrict__ bo,
                                              float* __restrict__ out)
{
    gemm_core(g_aoh, g_aol, g_wt2h + 3ull * 1048576, g_wt2l + 3ull * 1048576, bo, out);
}

// ---------------- fp32 -> bf16 hi/lo converters ----------------
__device__ __forceinline__ void split4(float4 v, __nv_bfloat16* h, __nv_bfloat16* l)
{
    __nv_bfloat16 h0 = __float2bfloat16(v.x);
    __nv_bfloat16 h1 = __float2bfloat16(v.y);
    __nv_bfloat16 h2 = __float2bfloat16(v.z);
    __nv_bfloat16 h3 = __float2bfloat16(v.w);
    h[0] = h0; h[1] = h1; h[2] = h2; h[3] = h3;
    l[0] = __float2bfloat16(v.x - __bfloat162float(h0));
    l[1] = __float2bfloat16(v.y - __bfloat162float(h1));
    l[2] = __float2bfloat16(v.z - __bfloat162float(h2));
    l[3] = __float2bfloat16(v.w - __bfloat162float(h3));
}

__global__ __launch_bounds__(256) void cvt_x_kernel(const float* __restrict__ x)
{
    size_t i = ((size_t)blockIdx.x * 256 + threadIdx.x) * 4;
    float4 v = *(const float4*)(x + i);
    __nv_bfloat16 h[4], l[4];
    split4(v, h, l);
    *(ulonglong1*)(g_xh + i) = *(ulonglong1*)h;
    *(ulonglong1*)(g_xl + i) = *(ulonglong1*)l;
}

__global__ __launch_bounds__(256) void cvt_ao_kernel()
{
    size_t i = ((size_t)blockIdx.x * 256 + threadIdx.x) * 4;
    float4 v = *(const float4*)(g_ao + i);
    __nv_bfloat16 h[4], l[4];
    split4(v, h, l);
    *(ulonglong1*)(g_aoh + i) = *(ulonglong1*)h;
    *(ulonglong1*)(g_aol + i) = *(ulonglong1*)l;
}

// ---------------- weight transpose + split: W[K,N] -> Wt hi/lo [N,K] (qp,kp,v,o) ----------------
__global__ __launch_bounds__(256) void wtrans_kernel(
    const float* __restrict__ Wqp, const float* __restrict__ Wkp,
    const float* __restrict__ Wv,  const float* __restrict__ Wo)
{
    __shared__ float tile[32][33];
    const float* W;
    switch (blockIdx.z) {
        case 0: W = Wqp; break;
        case 1: W = Wkp; break;
        case 2: W = Wv;  break;
        default: W = Wo; break;
    }
    int k0 = blockIdx.y * 32, n0 = blockIdx.x * 32;
    int tx = threadIdx.x & 31, ty = threadIdx.x >> 5;
#pragma unroll
    for (int i = 0; i < 4; i++)
        tile[ty + 8 * i][tx] = W[(size_t)(k0 + ty + 8 * i) * 1024 + n0 + tx];
    __syncthreads();
    __nv_bfloat16* th = g_wt2h + (size_t)blockIdx.z * 1048576;
    __nv_bfloat16* tl = g_wt2l + (size_t)blockIdx.z * 1048576;
#pragma unroll
    for (int i = 0; i < 4; i++) {
        int n = n0 + ty + 8 * i, k = k0 + tx;
        float v = tile[tx][ty + 8 * i];
        __nv_bfloat16 h = __float2bfloat16(v);
        th[(size_t)n * 1024 + k] = h;
        tl[(size_t)n * 1024 + k] = __float2bfloat16(v - __bfloat162float(h));
    }
}

// ---------------- wave normalization ----------------
__global__ __launch_bounds__(256) void wave_kernel()
{
    int gid  = blockIdx.x * 8 + (threadIdx.x >> 5);
    int lane = threadIdx.x & 31;
    int qk = gid >> 16;
    int r  = gid & 0xFFFF;
    int h = r & 15;
    int t = (r >> 4) & 2047;
    int b = r >> 15;

    const float* fb = g_wave + (size_t)qk * SLICE;
    const float* pb = g_wave + (size_t)(2 + qk) * SLICE;
    size_t base = ((size_t)(b * T_SEQ + t)) * DMODEL + h * NWAVE;
    float tf = (float)t;

    float f0 = fb[base + lane],      f1 = fb[base + lane + 32];
    float p0 = pb[base + lane],      p1 = pb[base + lane + 32];
    float w0 = sinf(__fadd_rn(__fmul_rn(f0, tf), p0));
    float w1 = sinf(__fadd_rn(__fmul_rn(f1, tf), p1));

    float s = w0 * w0 + w1 * w1;
#pragma unroll
    for (int o = 16; o > 0; o >>= 1) s += __shfl_xor_sync(0xffffffffu, s, o);
    float inv = 1.f / fmaxf(sqrtf(s), 1e-12f);

    float* dst = qk ? g_kn : g_qn;
    size_t ob = ((size_t)((b * HEADS + h) * T_SEQ + t)) * NWAVE;
    dst[ob + lane]      = w0 * inv;
    dst[ob + lane + 32] = w1 * inv;
}

// ---------------- pass 1: per-chunk KV sums ----------------
__global__ __launch_bounds__(256) void kvchunk_kernel()
{
    int c = blockIdx.x, bh = blockIdx.y;
    int b = bh >> 4, h = bh & 15;
    __shared__ float ks[CHUNK * NWAVE];
    __shared__ float vs[CHUNK * HDIM];
    const float* knp = g_kn + ((size_t)bh * T_SEQ + c * CHUNK) * NWAVE;
    const float* vp  = g_v + ((size_t)(b * T_SEQ + c * CHUNK)) * DMODEL + h * HDIM;
    for (int idx = threadIdx.x; idx < CHUNK * NWAVE; idx += 256) {
        ks[idx] = knp[idx];
        int s = idx >> 6, d = idx & 63;
        vs[idx] = vp[(size_t)s * DMODEL + d];
    }
    __syncthreads();
    int tw = (threadIdx.x >> 4) * 4, td = (threadIdx.x & 15) * 4;
    float acc[4][4] = {};
    for (int s = 0; s < CHUNK; s++) {
        float kr[4], vr[4];
#pragma unroll
        for (int i = 0; i < 4; i++) kr[i] = ks[s * NWAVE + tw + i];
#pragma unroll
        for (int j = 0; j < 4; j++) vr[j] = vs[s * HDIM + td + j];
#pragma unroll
        for (int i = 0; i < 4; i++)
#pragma unroll
            for (int j = 0; j < 4; j++)
                acc[i][j] = fmaf(kr[i], vr[j], acc[i][j]);
    }
    float* Mp = g_M + ((size_t)bh * NCHUNK + c) * (NWAVE * HDIM);
#pragma unroll
    for (int i = 0; i < 4; i++)
#pragma unroll
        for (int j = 0; j < 4; j++)
            Mp[(tw + i) * HDIM + td + j] = acc[i][j];
}

// ---------------- pass 2: exclusive prefix sum over chunks ----------------
__global__ __launch_bounds__(256) void prefix_kernel()
{
    int bh = blockIdx.y;
    int e = blockIdx.x * 256 + threadIdx.x;
    size_t base = (size_t)bh * NCHUNK * (NWAVE * HDIM) + e;
    float run = 0.f;
#pragma unroll
    for (int c = 0; c < NCHUNK; c++) {
        g_S[base + (size_t)c * (NWAVE * HDIM)] = run;
        run += g_M[base + (size_t)c * (NWAVE * HDIM)];
    }
}

// ---------------- pass 3: per-chunk output ----------------
__global__ __launch_bounds__(256) void attnout_kernel(const float* __restrict__ scale)
{
    int c = blockIdx.x, bh = blockIdx.y;
    int b = bh >> 4, h = bh & 15;
    int t0 = c * CHUNK;
    __shared__ float Xs[NWAVE * CHUNK];
    __shared__ float Ys[NWAVE * CHUNK];
    __shared__ float Zs[CHUNK * CHUNK];

    const float* qp_ = g_qn + ((size_t)bh * T_SEQ + t0) * NWAVE;
    const float* kp_ = g_kn + ((size_t)bh * T_SEQ + t0) * NWAVE;
    for (int idx = threadIdx.x; idx < CHUNK * NWAVE; idx += 256) {
        int t = idx >> 6, w = idx & 63;
        Xs[w * CHUNK + t] = qp_[idx];
        Ys[w * CHUNK + t] = kp_[idx];
    }
    __syncthreads();

    int ty = threadIdx.x >> 4, tx = threadIdx.x & 15;
    int tr = ty * 4, sc = tx * 4;

    {
        float acc[4][4] = {};
        for (int w = 0; w < NWAVE; w++) {
            float qr[4], kr[4];
#pragma unroll
            for (int i = 0; i < 4; i++) qr[i] = Xs[w * CHUNK + tr + i];
#pragma unroll
            for (int j = 0; j < 4; j++) kr[j] = Ys[w * CHUNK + sc + j];
#pragma unroll
            for (int i = 0; i < 4; i++)
#pragma unroll
                for (int j = 0; j < 4; j++)
                    acc[i][j] = fmaf(qr[i], kr[j], acc[i][j]);
        }
#pragma unroll
        for (int i = 0; i < 4; i++)
#pragma unroll
            for (int j = 0; j < 4; j++)
                Zs[(tr + i) * CHUNK + sc + j] = (sc + j <= tr + i) ? acc[i][j] : 0.f;
    }
    __syncthreads();

    const float* vp = g_v + ((size_t)(b * T_SEQ + t0)) * DMODEL + h * HDIM;
    for (int idx = threadIdx.x; idx < CHUNK * HDIM; idx += 256) {
        int s = idx >> 6, d = idx & 63;
        Ys[idx] = vp[(size_t)s * DMODEL + d];
    }
    __syncthreads();

    float out[4][4] = {};
    for (int s = 0; s < CHUNK; s++) {
        float ar[4], vr[4];
#pragma unroll
        for (int i = 0; i < 4; i++) ar[i] = Zs[(tr + i) * CHUNK + s];
#pragma unroll
        for (int j = 0; j < 4; j++) vr[j] = Ys[s * HDIM + sc + j];
#pragma unroll
        for (int i = 0; i < 4; i++)
#pragma unroll
            for (int j = 0; j < 4; j++)
                out[i][j] = fmaf(ar[i], vr[j], out[i][j]);
    }
    __syncthreads();

    const float* Sp = g_S + ((size_t)bh * NCHUNK + c) * (NWAVE * HDIM);
    for (int idx = threadIdx.x; idx < NWAVE * HDIM; idx += 256) Ys[idx] = Sp[idx];
    __syncthreads();

    for (int w = 0; w < NWAVE; w++) {
        float qr[4], sr[4];
#pragma unroll
        for (int i = 0; i < 4; i++) qr[i] = Xs[w * CHUNK + tr + i];
#pragma unroll
        for (int j = 0; j < 4; j++) sr[j] = Ys[w * HDIM + sc + j];
#pragma unroll
        for (int i = 0; i < 4; i++)
#pragma unroll
            for (int j = 0; j < 4; j++)
                out[i][j] = fmaf(qr[i], sr[j], out[i][j]);
    }

    float sch = scale[h];
    float* op = g_ao + ((size_t)(b * T_SEQ + t0)) * DMODEL + h * HDIM;
#pragma unroll
    for (int i = 0; i < 4; i++) {
        float fac = sch / sqrtf((float)(t0 + tr + i + 1));
        float4 o;
        o.x = out[i][0] * fac;
        o.y = out[i][1] * fac;
        o.z = out[i][2] * fac;
        o.w = out[i][3] * fac;
        *(float4*)(op + (size_t)(tr + i) * DMODEL + sc) = o;
    }
}

// ---------------- launch ----------------
extern "C" void kernel_launch(void* const* d_in, const int* in_sizes, int n_in,
                              void* d_out, int out_size)
{
    const float* x   = (const float*)d_in[0];
    const float* Wqf = (const float*)d_in[1];
    const float* bqf = (const float*)d_in[2];
    const float* Wkf = (const float*)d_in[3];
    const float* bkf = (const float*)d_in[4];
    const float* Wqp = (const float*)d_in[5];
    const float* bqp = (const float*)d_in[6];
    const float* Wkp = (const float*)d_in[7];
    const float* bkp = (const float*)d_in[8];
    const float* Wv  = (const float*)d_in[9];
    const float* bv  = (const float*)d_in[10];
    const float* Wo  = (const float*)d_in[11];
    const float* bo  = (const float*)d_in[12];
    const float* scl = (const float*)d_in[13];

    cudaFuncSetAttribute(proj_hmma, cudaFuncAttributeMaxDynamicSharedMemorySize, GEMM_DSMEM);
    cudaFuncSetAttribute(out_tc,    cudaFuncAttributeMaxDynamicSharedMemorySize, GEMM_DSMEM);

    cvt_x_kernel<<<SLICE / 1024, 256>>>(x);
    wtrans_kernel<<<dim3(32, 32, 4), 256>>>(Wqp, Wkp, Wv, Wo);
    proj_f32<<<dim3(8, 32, 2), 256>>>(x, Wqf, bqf, Wkf, bkf);
    proj_hmma<<<dim3(8, 32, 3), 256, GEMM_DSMEM>>>(bqp, bkp, bv);
    wave_kernel<<<(2 * BATCH * T_SEQ * HEADS) / 8, 256>>>();
    kvchunk_kernel<<<dim3(NCHUNK, BH), 256>>>();
    prefix_kernel<<<dim3(16, BH), 256>>>();
    attnout_kernel<<<dim3(NCHUNK, BH), 256>>>(scl);
    cvt_ao_kernel<<<SLICE / 1024, 256>>>();
    out_tc<<<dim3(8, 32), 256, GEMM_DSMEM>>>(bo, (float*)d_out);
}

// round 14
// speedup vs baseline: 1.4788x; 1.2382x over previous
#include <cuda_runtime.h>
#include <cuda_bf16.h>
#include <cstdint>
#include <math.h>

// Problem constants
#define T_SEQ 2048
#define BATCH 2
#define DMODEL 1024
#define HEADS 16
#define NWAVE 64
#define HDIM 64
#define ROWS (BATCH * T_SEQ)            // 4096
#define SLICE ((size_t)ROWS * DMODEL)   // 4194304 elements
#define BH (BATCH * HEADS)              // 32
#define CHUNK 64
#define NCHUNK (T_SEQ / CHUNK)          // 32

// HMMA GEMM smem layout: 64B rows (32 bf16), XOR-swizzled 16B chunks
#define ASZ2 4096                        // elems per array (128 rows x 32)
#define STG_BYTES (4 * ASZ2 * 2)         // 32768 B per stage (Ah, Al, Bh, Bl)
#define GEMM_DSMEM (3 * STG_BYTES)       // 98304 B (3-stage pipeline)

// ---------------- device scratch (no allocations allowed) ----------------
__device__ float g_wave[4 * SLICE];              // qf, kf, qp, kp raw projections
__device__ float g_v[SLICE];                     // v projection [b,t,h*64+d]
__device__ float g_qn[(size_t)BH * T_SEQ * NWAVE];
__device__ float g_kn[(size_t)BH * T_SEQ * NWAVE];
__device__ float g_M[(size_t)BH * NCHUNK * NWAVE * HDIM];
__device__ float g_S[(size_t)BH * NCHUNK * NWAVE * HDIM];
__device__ float g_ao[SLICE];                    // attention output

// 2-plane bf16 splits for HMMA GEMMs (qp, kp, v, out)
__device__ __nv_bfloat16 g_xh[SLICE], g_xl[SLICE];              // x hi/lo
__device__ __nv_bfloat16 g_wt2h[4u * 1024 * 1024];              // W^T hi: qp,kp,v,o
__device__ __nv_bfloat16 g_wt2l[4u * 1024 * 1024];              // W^T lo
__device__ __nv_bfloat16 g_aoh[SLICE], g_aol[SLICE];            // ao hi/lo

// ==================== packed f32x2 helpers (round-3 proven) ====================
__device__ __forceinline__ void ffma2(unsigned long long& d,
                                      unsigned long long a,
                                      unsigned long long b)
{
    asm("fma.rn.f32x2 %0, %1, %2, %0;" : "+l"(d) : "l"(a), "l"(b));
}
__device__ __forceinline__ unsigned long long pack2(float x)
{
    unsigned long long r;
    asm("mov.b64 %0, {%1, %1};" : "=l"(r) : "f"(x));
    return r;
}
__device__ __forceinline__ float2 unpack2(unsigned long long v)
{
    float2 r;
    asm("mov.b64 {%0, %1}, %2;" : "=f"(r.x), "=f"(r.y) : "l"(v));
    return r;
}

__device__ __forceinline__ uint32_t smem_u32(const void* p) {
    uint32_t a;
    asm("{ .reg .u64 t; cvta.to.shared.u64 t, %1; cvt.u32.u64 %0, t; }"
        : "=r"(a) : "l"(p));
    return a;
}

// ---------------- fp32 FFMA2 128x128 SGEMM (round-3 verbatim; PASSED) ----------------
__device__ __forceinline__ void sgemm128(const float* __restrict__ A,
                                         const float* __restrict__ Bw,
                                         const float* __restrict__ bias,
                                         float* __restrict__ C,
                                         int N, int K)
{
    __shared__ float As[16][128];
    __shared__ float Bs[16][128];
    const int tid  = threadIdx.x;
    const int row0 = blockIdx.y * 128;
    const int col0 = blockIdx.x * 128;
    const int arow = tid >> 1, acol = (tid & 1) * 8;
    const int brow = tid >> 4, bcol = (tid & 15) * 4;
    const int ty = tid >> 3;
    const int tx = tid & 7;

    unsigned long long acc[4][8];
#pragma unroll
    for (int i = 0; i < 4; i++)
#pragma unroll
        for (int j = 0; j < 8; j++) acc[i][j] = 0ULL;

    const float* aptr = A + (size_t)(row0 + arow) * K + acol;
    const float* bptr = Bw + (size_t)brow * N + col0 + bcol;

    float4 pa0 = *(const float4*)(aptr);
    float4 pa1 = *(const float4*)(aptr + 4);
    float4 pb0 = *(const float4*)(bptr);
    float4 pb1 = *(const float4*)(bptr + 64);

    for (int kk = 0; kk < K; kk += 16) {
        As[acol + 0][arow] = pa0.x;
        As[acol + 1][arow] = pa0.y;
        As[acol + 2][arow] = pa0.z;
        As[acol + 3][arow] = pa0.w;
        As[acol + 4][arow] = pa1.x;
        As[acol + 5][arow] = pa1.y;
        As[acol + 6][arow] = pa1.z;
        As[acol + 7][arow] = pa1.w;
        *(float4*)(&Bs[brow][bcol])      = pb0;
        *(float4*)(&Bs[brow][bcol + 64]) = pb1;
        __syncthreads();

        if (kk + 16 < K) {
            pa0 = *(const float4*)(aptr + kk + 16);
            pa1 = *(const float4*)(aptr + kk + 20);
            const float* bn = bptr + (size_t)(kk + 16) * N;
            pb0 = *(const float4*)(bn);
            pb1 = *(const float4*)(bn + 64);
        }

#pragma unroll
        for (int k = 0; k < 16; k++) {
            float4 av = *(const float4*)(&As[k][ty * 4]);
            unsigned long long ap2[4];
            ap2[0] = pack2(av.x);
            ap2[1] = pack2(av.y);
            ap2[2] = pack2(av.z);
            ap2[3] = pack2(av.w);
            ulonglong2 b0 = *(const ulonglong2*)(&Bs[k][tx * 4]);
            ulonglong2 b1 = *(const ulonglong2*)(&Bs[k][tx * 4 + 32]);
            ulonglong2 b2 = *(const ulonglong2*)(&Bs[k][tx * 4 + 64]);
            ulonglong2 b3 = *(const ulonglong2*)(&Bs[k][tx * 4 + 96]);
            unsigned long long bv[8] = {b0.x, b0.y, b1.x, b1.y,
                                        b2.x, b2.y, b3.x, b3.y};
#pragma unroll
            for (int i = 0; i < 4; i++)
#pragma unroll
                for (int j = 0; j < 8; j++)
                    ffma2(acc[i][j], ap2[i], bv[j]);
        }
        __syncthreads();
    }

#pragma unroll
    for (int i = 0; i < 4; i++) {
        int r = row0 + ty * 4 + i;
#pragma unroll
        for (int q = 0; q < 4; q++) {
            int c = col0 + q * 32 + tx * 4;
            float2 lo = unpack2(acc[i][2 * q]);
            float2 hi = unpack2(acc[i][2 * q + 1]);
            float4 bb = *(const float4*)(bias + c);
            float4 o;
            o.x = lo.x + bb.x;
            o.y = lo.y + bb.y;
            o.z = hi.x + bb.z;
            o.w = hi.y + bb.w;
            *(float4*)(C + (size_t)r * N + c) = o;
        }
    }
}

// fp32 frequency projections (precision-critical: feeds sin(f*t))
__global__ __launch_bounds__(256) void proj_f32(
    const float* __restrict__ x,
    const float* __restrict__ Wqf, const float* __restrict__ bqf,
    const float* __restrict__ Wkf, const float* __restrict__ bkf)
{
    int z = blockIdx.z;
    const float* W = z ? Wkf : Wqf;
    const float* b = z ? bkf : bqf;
    float* C = g_wave + (size_t)z * SLICE;
    sgemm128(x, W, b, C, DMODEL, DMODEL);
}

// ---------------- HMMA m16n8k16 bf16 -> fp32 ----------------
__device__ __forceinline__ void mma16816(float* d, const uint32_t* a, const uint32_t* b)
{
    asm volatile(
        "mma.sync.aligned.m16n8k16.row.col.f32.bf16.bf16.f32 "
        "{%0,%1,%2,%3}, {%4,%5,%6,%7}, {%8,%9}, {%0,%1,%2,%3};"
        : "+f"(d[0]), "+f"(d[1]), "+f"(d[2]), "+f"(d[3])
        : "r"(a[0]), "r"(a[1]), "r"(a[2]), "r"(a[3]), "r"(b[0]), "r"(b[1]));
}

#define LDSM_X4(r0, r1, r2, r3, addr) \
    asm volatile("ldmatrix.sync.aligned.m8n8.x4.shared.b16 {%0,%1,%2,%3}, [%4];" \
        : "=r"(r0), "=r"(r1), "=r"(r2), "=r"(r3) : "r"(addr))

#define CP16(dst, src) \
    asm volatile("cp.async.cg.shared.global [%0], [%1], 16;" \
        :: "r"(dst), "l"((const void*)(src)))
#define CP_COMMIT() asm volatile("cp.async.commit_group;" ::: "memory")

// ==================== cp.async + ldmatrix split-bf16 HMMA GEMM core ====================
// Same mma sequence as round-13 (numerics identical). 3-stage cp.async pipeline,
// XOR-swizzled 64B rows (conflict-free cp.async stores and LDSM reads).
__device__ __forceinline__ void gemm_core(
    const __nv_bfloat16* __restrict__ Ah, const __nv_bfloat16* __restrict__ Al,
    const __nv_bfloat16* __restrict__ Bh, const __nv_bfloat16* __restrict__ Bl,
    const float* __restrict__ bias, float* __restrict__ C)
{
    extern __shared__ __nv_bfloat16 sm[];
    const uint32_t smb = smem_u32(sm);
    const int tid = threadIdx.x;
    const int wid = tid >> 5, lane = tid & 31;
    const int wr = wid >> 2, wc = wid & 3;
    const int g = lane >> 2, t = lane & 3;
    const int m0 = blockIdx.y * 128, n0 = blockIdx.x * 128;

    float acc[4][4][4];
#pragma unroll
    for (int mt = 0; mt < 4; mt++)
#pragma unroll
        for (int nt = 0; nt < 4; nt++)
#pragma unroll
            for (int i = 0; i < 4; i++) acc[mt][nt][i] = 0.f;

    // ---- cp.async producer: thread -> (row lr, 32B half h), swizzled chunks ----
    const int lr = tid >> 1, hh = tid & 1;
    const int sw = (lr >> 1) & 3;
    const uint32_t q0 = (uint32_t)(((2 * hh) ^ sw) * 16);
    const uint32_t q1 = (uint32_t)(((2 * hh + 1) ^ sw) * 16);
    const uint32_t srow = smb + lr * 64;
    const __nv_bfloat16* g0 = Ah + (size_t)(m0 + lr) * 1024 + hh * 16;
    const __nv_bfloat16* g1 = Al + (size_t)(m0 + lr) * 1024 + hh * 16;
    const __nv_bfloat16* g2 = Bh + (size_t)(n0 + lr) * 1024 + hh * 16;
    const __nv_bfloat16* g3 = Bl + (size_t)(n0 + lr) * 1024 + hh * 16;

    auto fetch = [&](int st) {
        uint32_t sb = srow + (uint32_t)((st % 3) * STG_BYTES);
        size_t o = (size_t)st * 32;
        CP16(sb + q0,         g0 + o); CP16(sb + q1,         g0 + o + 8);
        CP16(sb + 8192 + q0,  g1 + o); CP16(sb + 8192 + q1,  g1 + o + 8);
        CP16(sb + 16384 + q0, g2 + o); CP16(sb + 16384 + q1, g2 + o + 8);
        CP16(sb + 24576 + q0, g3 + o); CP16(sb + 24576 + q1, g3 + o + 8);
        CP_COMMIT();
    };

    // ---- ldmatrix consumer lane addressing ----
    const int lm = lane >> 3, lrr = lane & 7;
    // A x4: matrices {a0,a1,a2,a3} = {(r0-7,k0-7),(r8-15,k0-7),(r0-7,k8-15),(r8-15,k8-15)}
    const int arowA = wr * 64 + (lm & 1) * 8 + lrr;   // + mt*16 (preserves swizzle)
    const int kcA   = lm >> 1;                        // + kk*2
    const int swA   = (arowA >> 1) & 3;
    const uint32_t baseA = smb + (uint32_t)(arowA * 64);
    // B x4 over nt pair: {b0(2j),b1(2j),b0(2j+1),b1(2j+1)}
    const int arowB = wc * 32 + (lm >> 1) * 8 + lrr;  // + j*16
    const int kcB   = lm & 1;                         // + kk*2
    const int swB   = (arowB >> 1) & 3;
    const uint32_t baseB = smb + 16384 + (uint32_t)(arowB * 64);

    auto compute = [&](int buf) {
        const uint32_t stb = (uint32_t)(buf * STG_BYTES);
#pragma unroll
        for (int kk = 0; kk < 2; kk++) {
            uint32_t ah[4][4], al[4][4];
            const uint32_t ka = (uint32_t)((((kcA + kk * 2) ^ swA)) * 16);
#pragma unroll
            for (int mt = 0; mt < 4; mt++) {
                uint32_t adr = baseA + stb + (uint32_t)(mt * 1024) + ka;
                LDSM_X4(ah[mt][0], ah[mt][1], ah[mt][2], ah[mt][3], adr);
                LDSM_X4(al[mt][0], al[mt][1], al[mt][2], al[mt][3], adr + 8192);
            }
            const uint32_t kb = (uint32_t)((((kcB + kk * 2) ^ swB)) * 16);
#pragma unroll
            for (int j = 0; j < 2; j++) {
                uint32_t bdr = baseB + stb + (uint32_t)(j * 1024) + kb;
                uint32_t bh[4], bl[4];
                LDSM_X4(bh[0], bh[1], bh[2], bh[3], bdr);
                LDSM_X4(bl[0], bl[1], bl[2], bl[3], bdr + 8192);
#pragma unroll
                for (int half = 0; half < 2; half++) {
                    int nt = 2 * j + half;
#pragma unroll
                    for (int mt = 0; mt < 4; mt++) {
                        mma16816(acc[mt][nt], ah[mt], bh + 2 * half);
                        mma16816(acc[mt][nt], ah[mt], bl + 2 * half);
                        mma16816(acc[mt][nt], al[mt], bh + 2 * half);
                    }
                }
            }
        }
    };

    fetch(0);
    fetch(1);
    for (int st = 0; st < 32; st++) {
        if (st < 31) asm volatile("cp.async.wait_group 1;" ::: "memory");
        else         asm volatile("cp.async.wait_group 0;" ::: "memory");
        __syncthreads();
        compute(st % 3);
        if (st + 2 < 32) fetch(st + 2);
    }

    // ---- epilogue ----
#pragma unroll
    for (int mt = 0; mt < 4; mt++) {
#pragma unroll
        for (int nt = 0; nt < 4; nt++) {
            int row = m0 + wr * 64 + mt * 16 + g;
            int col = n0 + wc * 32 + nt * 8 + 2 * t;
            float2 bb = *(const float2*)(bias + col);
            float2 o0, o1;
            o0.x = acc[mt][nt][0] + bb.x;
            o0.y = acc[mt][nt][1] + bb.y;
            o1.x = acc[mt][nt][2] + bb.x;
            o1.y = acc[mt][nt][3] + bb.y;
            *(float2*)(C + (size_t)row * 1024 + col)       = o0;
            *(float2*)(C + (size_t)(row + 8) * 1024 + col) = o1;
        }
    }
}

// HMMA projections: qp (z=0), kp (z=1), v (z=2)
__global__ __launch_bounds__(256, 2) void proj_hmma(
    const float* __restrict__ bqp, const float* __restrict__ bkp,
    const float* __restrict__ bv)
{
    int z = blockIdx.z;
    const float* bias = (z == 0) ? bqp : (z == 1) ? bkp : bv;
    float* C = (z == 0) ? g_wave + 2 * SLICE : (z == 1) ? g_wave + 3 * SLICE : g_v;
    gemm_core(g_xh, g_xl,
              g_wt2h + (size_t)z * 1048576, g_wt2l + (size_t)z * 1048576, bias, C);
}

__global__ __launch_bounds__(256, 2) void out_tc(const float* __restrict__ bo,
                                                 float* __restrict__ out)
{
    gemm_core(g_aoh, g_aol, g_wt2h + 3ull * 1048576, g_wt2l + 3ull * 1048576, bo, out);
}

// ---------------- fp32 -> bf16 hi/lo converters ----------------
__device__ __forceinline__ void split4(float4 v, __nv_bfloat16* h, __nv_bfloat16* l)
{
    __nv_bfloat16 h0 = __float2bfloat16(v.x);
    __nv_bfloat16 h1 = __float2bfloat16(v.y);
    __nv_bfloat16 h2 = __float2bfloat16(v.z);
    __nv_bfloat16 h3 = __float2bfloat16(v.w);
    h[0] = h0; h[1] = h1; h[2] = h2; h[3] = h3;
    l[0] = __float2bfloat16(v.x - __bfloat162float(h0));
    l[1] = __float2bfloat16(v.y - __bfloat162float(h1));
    l[2] = __float2bfloat16(v.z - __bfloat162float(h2));
    l[3] = __float2bfloat16(v.w - __bfloat162float(h3));
}

__global__ __launch_bounds__(256) void cvt_x_kernel(const float* __restrict__ x)
{
    size_t i = ((size_t)blockIdx.x * 256 + threadIdx.x) * 4;
    float4 v = *(const float4*)(x + i);
    __nv_bfloat16 h[4], l[4];
    split4(v, h, l);
    *(ulonglong1*)(g_xh + i) = *(ulonglong1*)h;
    *(ulonglong1*)(g_xl + i) = *(ulonglong1*)l;
}

__global__ __launch_bounds__(256) void cvt_ao_kernel()
{
    size_t i = ((size_t)blockIdx.x * 256 + threadIdx.x) * 4;
    float4 v = *(const float4*)(g_ao + i);
    __nv_bfloat16 h[4], l[4];
    split4(v, h, l);
    *(ulonglong1*)(g_aoh + i) = *(ulonglong1*)h;
    *(ulonglong1*)(g_aol + i) = *(ulonglong1*)l;
}

// ---------------- weight transpose + split: W[K,N] -> Wt hi/lo [N,K] (qp,kp,v,o) ----------------
__global__ __launch_bounds__(256) void wtrans_kernel(
    const float* __restrict__ Wqp, const float* __restrict__ Wkp,
    const float* __restrict__ Wv,  const float* __restrict__ Wo)
{
    __shared__ float tile[32][33];
    const float* W;
    switch (blockIdx.z) {
        case 0: W = Wqp; break;
        case 1: W = Wkp; break;
        case 2: W = Wv;  break;
        default: W = Wo; break;
    }
    int k0 = blockIdx.y * 32, n0 = blockIdx.x * 32;
    int tx = threadIdx.x & 31, ty = threadIdx.x >> 5;
#pragma unroll
    for (int i = 0; i < 4; i++)
        tile[ty + 8 * i][tx] = W[(size_t)(k0 + ty + 8 * i) * 1024 + n0 + tx];
    __syncthreads();
    __nv_bfloat16* th = g_wt2h + (size_t)blockIdx.z * 1048576;
    __nv_bfloat16* tl = g_wt2l + (size_t)blockIdx.z * 1048576;
#pragma unroll
    for (int i = 0; i < 4; i++) {
        int n = n0 + ty + 8 * i, k = k0 + tx;
        float v = tile[tx][ty + 8 * i];
        __nv_bfloat16 h = __float2bfloat16(v);
        th[(size_t)n * 1024 + k] = h;
        tl[(size_t)n * 1024 + k] = __float2bfloat16(v - __bfloat162float(h));
    }
}

// ---------------- wave normalization ----------------
__global__ __launch_bounds__(256) void wave_kernel()
{
    int gid  = blockIdx.x * 8 + (threadIdx.x >> 5);
    int lane = threadIdx.x & 31;
    int qk = gid >> 16;
    int r  = gid & 0xFFFF;
    int h = r & 15;
    int t = (r >> 4) & 2047;
    int b = r >> 15;

    const float* fb = g_wave + (size_t)qk * SLICE;
    const float* pb = g_wave + (size_t)(2 + qk) * SLICE;
    size_t base = ((size_t)(b * T_SEQ + t)) * DMODEL + h * NWAVE;
    float tf = (float)t;

    float f0 = fb[base + lane],      f1 = fb[base + lane + 32];
    float p0 = pb[base + lane],      p1 = pb[base + lane + 32];
    float w0 = sinf(__fadd_rn(__fmul_rn(f0, tf), p0));
    float w1 = sinf(__fadd_rn(__fmul_rn(f1, tf), p1));

    float s = w0 * w0 + w1 * w1;
#pragma unroll
    for (int o = 16; o > 0; o >>= 1) s += __shfl_xor_sync(0xffffffffu, s, o);
    float inv = 1.f / fmaxf(sqrtf(s), 1e-12f);

    float* dst = qk ? g_kn : g_qn;
    size_t ob = ((size_t)((b * HEADS + h) * T_SEQ + t)) * NWAVE;
    dst[ob + lane]      = w0 * inv;
    dst[ob + lane + 32] = w1 * inv;
}

// ---------------- pass 1: per-chunk KV sums ----------------
__global__ __launch_bounds__(256) void kvchunk_kernel()
{
    int c = blockIdx.x, bh = blockIdx.y;
    int b = bh >> 4, h = bh & 15;
    __shared__ float ks[CHUNK * NWAVE];
    __shared__ float vs[CHUNK * HDIM];
    const float* knp = g_kn + ((size_t)bh * T_SEQ + c * CHUNK) * NWAVE;
    const float* vp  = g_v + ((size_t)(b * T_SEQ + c * CHUNK)) * DMODEL + h * HDIM;
    for (int idx = threadIdx.x; idx < CHUNK * NWAVE; idx += 256) {
        ks[idx] = knp[idx];
        int s = idx >> 6, d = idx & 63;
        vs[idx] = vp[(size_t)s * DMODEL + d];
    }
    __syncthreads();
    int tw = (threadIdx.x >> 4) * 4, td = (threadIdx.x & 15) * 4;
    float acc[4][4] = {};
    for (int s = 0; s < CHUNK; s++) {
        float kr[4], vr[4];
#pragma unroll
        for (int i = 0; i < 4; i++) kr[i] = ks[s * NWAVE + tw + i];
#pragma unroll
        for (int j = 0; j < 4; j++) vr[j] = vs[s * HDIM + td + j];
#pragma unroll
        for (int i = 0; i < 4; i++)
#pragma unroll
            for (int j = 0; j < 4; j++)
                acc[i][j] = fmaf(kr[i], vr[j], acc[i][j]);
    }
    float* Mp = g_M + ((size_t)bh * NCHUNK + c) * (NWAVE * HDIM);
#pragma unroll
    for (int i = 0; i < 4; i++)
#pragma unroll
        for (int j = 0; j < 4; j++)
            Mp[(tw + i) * HDIM + td + j] = acc[i][j];
}

// ---------------- pass 2: exclusive prefix sum over chunks ----------------
__global__ __launch_bounds__(256) void prefix_kernel()
{
    int bh = blockIdx.y;
    int e = blockIdx.x * 256 + threadIdx.x;
    size_t base = (size_t)bh * NCHUNK * (NWAVE * HDIM) + e;
    float run = 0.f;
#pragma unroll
    for (int c = 0; c < NCHUNK; c++) {
        g_S[base + (size_t)c * (NWAVE * HDIM)] = run;
        run += g_M[base + (size_t)c * (NWAVE * HDIM)];
    }
}

// ---------------- pass 3: per-chunk output ----------------
__global__ __launch_bounds__(256) void attnout_kernel(const float* __restrict__ scale)
{
    int c = blockIdx.x, bh = blockIdx.y;
    int b = bh >> 4, h = bh & 15;
    int t0 = c * CHUNK;
    __shared__ float Xs[NWAVE * CHUNK];
    __shared__ float Ys[NWAVE * CHUNK];
    __shared__ float Zs[CHUNK * CHUNK];

    const float* qp_ = g_qn + ((size_t)bh * T_SEQ + t0) * NWAVE;
    const float* kp_ = g_kn + ((size_t)bh * T_SEQ + t0) * NWAVE;
    for (int idx = threadIdx.x; idx < CHUNK * NWAVE; idx += 256) {
        int t = idx >> 6, w = idx & 63;
        Xs[w * CHUNK + t] = qp_[idx];
        Ys[w * CHUNK + t] = kp_[idx];
    }
    __syncthreads();

    int ty = threadIdx.x >> 4, tx = threadIdx.x & 15;
    int tr = ty * 4, sc = tx * 4;

    {
        float acc[4][4] = {};
        for (int w = 0; w < NWAVE; w++) {
            float qr[4], kr[4];
#pragma unroll
            for (int i = 0; i < 4; i++) qr[i] = Xs[w * CHUNK + tr + i];
#pragma unroll
            for (int j = 0; j < 4; j++) kr[j] = Ys[w * CHUNK + sc + j];
#pragma unroll
            for (int i = 0; i < 4; i++)
#pragma unroll
                for (int j = 0; j < 4; j++)
                    acc[i][j] = fmaf(qr[i], kr[j], acc[i][j]);
        }
#pragma unroll
        for (int i = 0; i < 4; i++)
#pragma unroll
            for (int j = 0; j < 4; j++)
                Zs[(tr + i) * CHUNK + sc + j] = (sc + j <= tr + i) ? acc[i][j] : 0.f;
    }
    __syncthreads();

    const float* vp = g_v + ((size_t)(b * T_SEQ + t0)) * DMODEL + h * HDIM;
    for (int idx = threadIdx.x; idx < CHUNK * HDIM; idx += 256) {
        int s = idx >> 6, d = idx & 63;
        Ys[idx] = vp[(size_t)s * DMODEL + d];
    }
    __syncthreads();

    float out[4][4] = {};
    for (int s = 0; s < CHUNK; s++) {
        float ar[4], vr[4];
#pragma unroll
        for (int i = 0; i < 4; i++) ar[i] = Zs[(tr + i) * CHUNK + s];
#pragma unroll
        for (int j = 0; j < 4; j++) vr[j] = Ys[s * HDIM + sc + j];
#pragma unroll
        for (int i = 0; i < 4; i++)
#pragma unroll
            for (int j = 0; j < 4; j++)
                out[i][j] = fmaf(ar[i], vr[j], out[i][j]);
    }
    __syncthreads();

    const float* Sp = g_S + ((size_t)bh * NCHUNK + c) * (NWAVE * HDIM);
    for (int idx = threadIdx.x; idx < NWAVE * HDIM; idx += 256) Ys[idx] = Sp[idx];
    __syncthreads();

    for (int w = 0; w < NWAVE; w++) {
        float qr[4], sr[4];
#pragma unroll
        for (int i = 0; i < 4; i++) qr[i] = Xs[w * CHUNK + tr + i];
#pragma unroll
        for (int j = 0; j < 4; j++) sr[j] = Ys[w * HDIM + sc + j];
#pragma unroll
        for (int i = 0; i < 4; i++)
#pragma unroll
            for (int j = 0; j < 4; j++)
                out[i][j] = fmaf(qr[i], sr[j], out[i][j]);
    }

    float sch = scale[h];
    float* op = g_ao + ((size_t)(b * T_SEQ + t0)) * DMODEL + h * HDIM;
#pragma unroll
    for (int i = 0; i < 4; i++) {
        float fac = sch / sqrtf((float)(t0 + tr + i + 1));
        float4 o;
        o.x = out[i][0] * fac;
        o.y = out[i][1] * fac;
        o.z = out[i][2] * fac;
        o.w = out[i][3] * fac;
        *(float4*)(op + (size_t)(tr + i) * DMODEL + sc) = o;
    }
}

// ---------------- launch ----------------
extern "C" void kernel_launch(void* const* d_in, const int* in_sizes, int n_in,
                              void* d_out, int out_size)
{
    const float* x   = (const float*)d_in[0];
    const float* Wqf = (const float*)d_in[1];
    const float* bqf = (const float*)d_in[2];
    const float* Wkf = (const float*)d_in[3];
    const float* bkf = (const float*)d_in[4];
    const float* Wqp = (const float*)d_in[5];
    const float* bqp = (const float*)d_in[6];
    const float* Wkp = (const float*)d_in[7];
    const float* bkp = (const float*)d_in[8];
    const float* Wv  = (const float*)d_in[9];
    const float* bv  = (const float*)d_in[10];
    const float* Wo  = (const float*)d_in[11];
    const float* bo  = (const float*)d_in[12];
    const float* scl = (const float*)d_in[13];

    cudaFuncSetAttribute(proj_hmma, cudaFuncAttributeMaxDynamicSharedMemorySize, GEMM_DSMEM);
    cudaFuncSetAttribute(out_tc,    cudaFuncAttributeMaxDynamicSharedMemorySize, GEMM_DSMEM);

    cvt_x_kernel<<<SLICE / 1024, 256>>>(x);
    wtrans_kernel<<<dim3(32, 32, 4), 256>>>(Wqp, Wkp, Wv, Wo);
    proj_f32<<<dim3(8, 32, 2), 256>>>(x, Wqf, bqf, Wkf, bkf);
    proj_hmma<<<dim3(8, 32, 3), 256, GEMM_DSMEM>>>(bqp, bkp, bv);
    wave_kernel<<<(2 * BATCH * T_SEQ * HEADS) / 8, 256>>>();
    kvchunk_kernel<<<dim3(NCHUNK, BH), 256>>>();
    prefix_kernel<<<dim3(16, BH), 256>>>();
    attnout_kernel<<<dim3(NCHUNK, BH), 256>>>(scl);
    cvt_ao_kernel<<<SLICE / 1024, 256>>>();
    out_tc<<<dim3(8, 32), 256, GEMM_DSMEM>>>(bo, (float*)d_out);
}

// round 15
// speedup vs baseline: 1.5186x; 1.0269x over previous
#include <cuda_runtime.h>
#include <cuda_bf16.h>
#include <cstdint>
#include <math.h>

// Problem constants
#define T_SEQ 2048
#define BATCH 2
#define DMODEL 1024
#define HEADS 16
#define NWAVE 64
#define HDIM 64
#define ROWS (BATCH * T_SEQ)            // 4096
#define SLICE ((size_t)ROWS * DMODEL)   // 4194304 elements
#define BH (BATCH * HEADS)              // 32
#define CHUNK 64
#define NCHUNK (T_SEQ / CHUNK)          // 32

// HMMA GEMM smem layout: 64B rows (32 bf16), XOR-swizzled 16B chunks
#define ASZ2 4096                        // elems per array (128 rows x 32)
#define STG_BYTES (4 * ASZ2 * 2)         // 32768 B per stage (Ah, Al, Bh, Bl)
#define GEMM_DSMEM (3 * STG_BYTES)       // 98304 B (3-stage pipeline; fp32 path uses 16KB)

// ---------------- device scratch (no allocations allowed) ----------------
__device__ float g_wave[4 * SLICE];              // qf, kf, qp, kp raw projections
__device__ float g_v[SLICE];                     // v projection [b,t,h*64+d]
__device__ float g_qn[(size_t)BH * T_SEQ * NWAVE];
__device__ float g_kn[(size_t)BH * T_SEQ * NWAVE];
__device__ float g_M[(size_t)BH * NCHUNK * NWAVE * HDIM];
__device__ float g_S[(size_t)BH * NCHUNK * NWAVE * HDIM];
__device__ float g_ao[SLICE];                    // attention output

// 2-plane bf16 splits for HMMA GEMMs (qp, kp, v, out)
__device__ __nv_bfloat16 g_xh[SLICE], g_xl[SLICE];              // x hi/lo
__device__ __nv_bfloat16 g_wt2h[4u * 1024 * 1024];              // W^T hi: qp,kp,v,o
__device__ __nv_bfloat16 g_wt2l[4u * 1024 * 1024];              // W^T lo
__device__ __nv_bfloat16 g_aoh[SLICE], g_aol[SLICE];            // ao hi/lo

// ==================== packed f32x2 helpers (round-3 proven) ====================
__device__ __forceinline__ void ffma2(unsigned long long& d,
                                      unsigned long long a,
                                      unsigned long long b)
{
    asm("fma.rn.f32x2 %0, %1, %2, %0;" : "+l"(d) : "l"(a), "l"(b));
}
__device__ __forceinline__ unsigned long long pack2(float x)
{
    unsigned long long r;
    asm("mov.b64 %0, {%1, %1};" : "=l"(r) : "f"(x));
    return r;
}
__device__ __forceinline__ float2 unpack2(unsigned long long v)
{
    float2 r;
    asm("mov.b64 {%0, %1}, %2;" : "=f"(r.x), "=f"(r.y) : "l"(v));
    return r;
}

__device__ __forceinline__ uint32_t smem_u32(const void* p) {
    uint32_t a;
    asm("{ .reg .u64 t; cvta.to.shared.u64 t, %1; cvt.u32.u64 %0, t; }"
        : "=r"(a) : "l"(p));
    return a;
}

// ---------------- fp32 FFMA2 128x128 SGEMM (round-3 numerics; smem from dynamic) ----------------
__device__ __forceinline__ void sgemm128(const float* __restrict__ A,
                                         const float* __restrict__ Bw,
                                         const float* __restrict__ bias,
                                         float* __restrict__ C,
                                         int N, int K, int bx, int by)
{
    extern __shared__ char dsmem_raw[];
    float* As = (float*)dsmem_raw;            // [16][128]
    float* Bs = As + 16 * 128;                 // [16][128]
    const int tid  = threadIdx.x;
    const int row0 = by * 128;
    const int col0 = bx * 128;
    const int arow = tid >> 1, acol = (tid & 1) * 8;
    const int brow = tid >> 4, bcol = (tid & 15) * 4;
    const int ty = tid >> 3;
    const int tx = tid & 7;

    unsigned long long acc[4][8];
#pragma unroll
    for (int i = 0; i < 4; i++)
#pragma unroll
        for (int j = 0; j < 8; j++) acc[i][j] = 0ULL;

    const float* aptr = A + (size_t)(row0 + arow) * K + acol;
    const float* bptr = Bw + (size_t)brow * N + col0 + bcol;

    float4 pa0 = *(const float4*)(aptr);
    float4 pa1 = *(const float4*)(aptr + 4);
    float4 pb0 = *(const float4*)(bptr);
    float4 pb1 = *(const float4*)(bptr + 64);

    for (int kk = 0; kk < K; kk += 16) {
        As[(acol + 0) * 128 + arow] = pa0.x;
        As[(acol + 1) * 128 + arow] = pa0.y;
        As[(acol + 2) * 128 + arow] = pa0.z;
        As[(acol + 3) * 128 + arow] = pa0.w;
        As[(acol + 4) * 128 + arow] = pa1.x;
        As[(acol + 5) * 128 + arow] = pa1.y;
        As[(acol + 6) * 128 + arow] = pa1.z;
        As[(acol + 7) * 128 + arow] = pa1.w;
        *(float4*)(&Bs[brow * 128 + bcol])      = pb0;
        *(float4*)(&Bs[brow * 128 + bcol + 64]) = pb1;
        __syncthreads();

        if (kk + 16 < K) {
            pa0 = *(const float4*)(aptr + kk + 16);
            pa1 = *(const float4*)(aptr + kk + 20);
            const float* bn = bptr + (size_t)(kk + 16) * N;
            pb0 = *(const float4*)(bn);
            pb1 = *(const float4*)(bn + 64);
        }

#pragma unroll
        for (int k = 0; k < 16; k++) {
            float4 av = *(const float4*)(&As[k * 128 + ty * 4]);
            unsigned long long ap2[4];
            ap2[0] = pack2(av.x);
            ap2[1] = pack2(av.y);
            ap2[2] = pack2(av.z);
            ap2[3] = pack2(av.w);
            ulonglong2 b0 = *(const ulonglong2*)(&Bs[k * 128 + tx * 4]);
            ulonglong2 b1 = *(const ulonglong2*)(&Bs[k * 128 + tx * 4 + 32]);
            ulonglong2 b2 = *(const ulonglong2*)(&Bs[k * 128 + tx * 4 + 64]);
            ulonglong2 b3 = *(const ulonglong2*)(&Bs[k * 128 + tx * 4 + 96]);
            unsigned long long bv[8] = {b0.x, b0.y, b1.x, b1.y,
                                        b2.x, b2.y, b3.x, b3.y};
#pragma unroll
            for (int i = 0; i < 4; i++)
#pragma unroll
                for (int j = 0; j < 8; j++)
                    ffma2(acc[i][j], ap2[i], bv[j]);
        }
        __syncthreads();
    }

#pragma unroll
    for (int i = 0; i < 4; i++) {
        int r = row0 + ty * 4 + i;
#pragma unroll
        for (int q = 0; q < 4; q++) {
            int c = col0 + q * 32 + tx * 4;
            float2 lo = unpack2(acc[i][2 * q]);
            float2 hi = unpack2(acc[i][2 * q + 1]);
            float4 bb = *(const float4*)(bias + c);
            float4 o;
            o.x = lo.x + bb.x;
            o.y = lo.y + bb.y;
            o.z = hi.x + bb.z;
            o.w = hi.y + bb.w;
            *(float4*)(C + (size_t)r * N + c) = o;
        }
    }
}

// ---------------- HMMA m16n8k16 bf16 -> fp32 ----------------
__device__ __forceinline__ void mma16816(float* d, const uint32_t* a, const uint32_t* b)
{
    asm volatile(
        "mma.sync.aligned.m16n8k16.row.col.f32.bf16.bf16.f32 "
        "{%0,%1,%2,%3}, {%4,%5,%6,%7}, {%8,%9}, {%0,%1,%2,%3};"
        : "+f"(d[0]), "+f"(d[1]), "+f"(d[2]), "+f"(d[3])
        : "r"(a[0]), "r"(a[1]), "r"(a[2]), "r"(a[3]), "r"(b[0]), "r"(b[1]));
}

#define LDSM_X4(r0, r1, r2, r3, addr) \
    asm volatile("ldmatrix.sync.aligned.m8n8.x4.shared.b16 {%0,%1,%2,%3}, [%4];" \
        : "=r"(r0), "=r"(r1), "=r"(r2), "=r"(r3) : "r"(addr))

#define CP16(dst, src) \
    asm volatile("cp.async.cg.shared.global [%0], [%1], 16;" \
        :: "r"(dst), "l"((const void*)(src)))
#define CP_COMMIT() asm volatile("cp.async.commit_group;" ::: "memory")

// ==================== cp.async + ldmatrix split-bf16 HMMA GEMM core (round-14 verbatim) ====================
__device__ __forceinline__ void gemm_core(
    const __nv_bfloat16* __restrict__ Ah, const __nv_bfloat16* __restrict__ Al,
    const __nv_bfloat16* __restrict__ Bh, const __nv_bfloat16* __restrict__ Bl,
    const float* __restrict__ bias, float* __restrict__ C, int bx, int by)
{
    extern __shared__ char dsmem_raw[];
    __nv_bfloat16* sm = (__nv_bfloat16*)dsmem_raw;
    const uint32_t smb = smem_u32(sm);
    const int tid = threadIdx.x;
    const int wid = tid >> 5, lane = tid & 31;
    const int wr = wid >> 2, wc = wid & 3;
    const int g = lane >> 2, t = lane & 3;
    const int m0 = by * 128, n0 = bx * 128;

    float acc[4][4][4];
#pragma unroll
    for (int mt = 0; mt < 4; mt++)
#pragma unroll
        for (int nt = 0; nt < 4; nt++)
#pragma unroll
            for (int i = 0; i < 4; i++) acc[mt][nt][i] = 0.f;

    const int lr = tid >> 1, hh = tid & 1;
    const int sw = (lr >> 1) & 3;
    const uint32_t q0 = (uint32_t)(((2 * hh) ^ sw) * 16);
    const uint32_t q1 = (uint32_t)(((2 * hh + 1) ^ sw) * 16);
    const uint32_t srow = smb + lr * 64;
    const __nv_bfloat16* g0 = Ah + (size_t)(m0 + lr) * 1024 + hh * 16;
    const __nv_bfloat16* g1 = Al + (size_t)(m0 + lr) * 1024 + hh * 16;
    const __nv_bfloat16* g2 = Bh + (size_t)(n0 + lr) * 1024 + hh * 16;
    const __nv_bfloat16* g3 = Bl + (size_t)(n0 + lr) * 1024 + hh * 16;

    auto fetch = [&](int st) {
        uint32_t sb = srow + (uint32_t)((st % 3) * STG_BYTES);
        size_t o = (size_t)st * 32;
        CP16(sb + q0,         g0 + o); CP16(sb + q1,         g0 + o + 8);
        CP16(sb + 8192 + q0,  g1 + o); CP16(sb + 8192 + q1,  g1 + o + 8);
        CP16(sb + 16384 + q0, g2 + o); CP16(sb + 16384 + q1, g2 + o + 8);
        CP16(sb + 24576 + q0, g3 + o); CP16(sb + 24576 + q1, g3 + o + 8);
        CP_COMMIT();
    };

    const int lm = lane >> 3, lrr = lane & 7;
    const int arowA = wr * 64 + (lm & 1) * 8 + lrr;
    const int kcA   = lm >> 1;
    const int swA   = (arowA >> 1) & 3;
    const uint32_t baseA = smb + (uint32_t)(arowA * 64);
    const int arowB = wc * 32 + (lm >> 1) * 8 + lrr;
    const int kcB   = lm & 1;
    const int swB   = (arowB >> 1) & 3;
    const uint32_t baseB = smb + 16384 + (uint32_t)(arowB * 64);

    auto compute = [&](int buf) {
        const uint32_t stb = (uint32_t)(buf * STG_BYTES);
#pragma unroll
        for (int kk = 0; kk < 2; kk++) {
            uint32_t ah[4][4], al[4][4];
            const uint32_t ka = (uint32_t)((((kcA + kk * 2) ^ swA)) * 16);
#pragma unroll
            for (int mt = 0; mt < 4; mt++) {
                uint32_t adr = baseA + stb + (uint32_t)(mt * 1024) + ka;
                LDSM_X4(ah[mt][0], ah[mt][1], ah[mt][2], ah[mt][3], adr);
                LDSM_X4(al[mt][0], al[mt][1], al[mt][2], al[mt][3], adr + 8192);
            }
            const uint32_t kb = (uint32_t)((((kcB + kk * 2) ^ swB)) * 16);
#pragma unroll
            for (int j = 0; j < 2; j++) {
                uint32_t bdr = baseB + stb + (uint32_t)(j * 1024) + kb;
                uint32_t bh[4], bl[4];
                LDSM_X4(bh[0], bh[1], bh[2], bh[3], bdr);
                LDSM_X4(bl[0], bl[1], bl[2], bl[3], bdr + 8192);
#pragma unroll
                for (int half = 0; half < 2; half++) {
                    int nt = 2 * j + half;
#pragma unroll
                    for (int mt = 0; mt < 4; mt++) {
                        mma16816(acc[mt][nt], ah[mt], bh + 2 * half);
                        mma16816(acc[mt][nt], ah[mt], bl + 2 * half);
                        mma16816(acc[mt][nt], al[mt], bh + 2 * half);
                    }
                }
            }
        }
    };

    fetch(0);
    fetch(1);
    for (int st = 0; st < 32; st++) {
        if (st < 31) asm volatile("cp.async.wait_group 1;" ::: "memory");
        else         asm volatile("cp.async.wait_group 0;" ::: "memory");
        __syncthreads();
        compute(st % 3);
        if (st + 2 < 32) fetch(st + 2);
    }

#pragma unroll
    for (int mt = 0; mt < 4; mt++) {
#pragma unroll
        for (int nt = 0; nt < 4; nt++) {
            int row = m0 + wr * 64 + mt * 16 + g;
            int col = n0 + wc * 32 + nt * 8 + 2 * t;
            float2 bb = *(const float2*)(bias + col);
            float2 o0, o1;
            o0.x = acc[mt][nt][0] + bb.x;
            o0.y = acc[mt][nt][1] + bb.y;
            o1.x = acc[mt][nt][2] + bb.x;
            o1.y = acc[mt][nt][3] + bb.y;
            *(float2*)(C + (size_t)row * 1024 + col)       = o0;
            *(float2*)(C + (size_t)(row + 8) * 1024 + col) = o1;
        }
    }
}

// ---------------- fused projection kernel: fp32 + HMMA jobs interleaved ----------------
// 1280 CTAs: job = blockIdx.x % 5 (0,1: fp32 qf/kf; 2,3,4: HMMA qp/kp/v), tile = /5.
__global__ __launch_bounds__(256, 2) void proj_all(
    const float* __restrict__ x,
    const float* __restrict__ Wqf, const float* __restrict__ bqf,
    const float* __restrict__ Wkf, const float* __restrict__ bkf,
    const float* __restrict__ bqp, const float* __restrict__ bkp,
    const float* __restrict__ bv)
{
    int job  = blockIdx.x % 5;
    int tile = blockIdx.x / 5;
    int bx = tile & 7, by = tile >> 3;

    if (job < 2) {
        const float* W = job ? Wkf : Wqf;
        const float* b = job ? bkf : bqf;
        float* C = g_wave + (size_t)job * SLICE;
        sgemm128(x, W, b, C, DMODEL, DMODEL, bx, by);
    } else {
        int z = job - 2;
        const float* bias = (z == 0) ? bqp : (z == 1) ? bkp : bv;
        float* C = (z == 0) ? g_wave + 2 * SLICE : (z == 1) ? g_wave + 3 * SLICE : g_v;
        gemm_core(g_xh, g_xl,
                  g_wt2h + (size_t)z * 1048576, g_wt2l + (size_t)z * 1048576,
                  bias, C, bx, by);
    }
}

__global__ __launch_bounds__(256, 2) void out_tc(const float* __restrict__ bo,
                                                 float* __restrict__ out)
{
    gemm_core(g_aoh, g_aol, g_wt2h + 3ull * 1048576, g_wt2l + 3ull * 1048576, bo, out,
              blockIdx.x, blockIdx.y);
}

// ---------------- fp32 -> bf16 hi/lo converters ----------------
__device__ __forceinline__ void split4(float4 v, __nv_bfloat16* h, __nv_bfloat16* l)
{
    __nv_bfloat16 h0 = __float2bfloat16(v.x);
    __nv_bfloat16 h1 = __float2bfloat16(v.y);
    __nv_bfloat16 h2 = __float2bfloat16(v.z);
    __nv_bfloat16 h3 = __float2bfloat16(v.w);
    h[0] = h0; h[1] = h1; h[2] = h2; h[3] = h3;
    l[0] = __float2bfloat16(v.x - __bfloat162float(h0));
    l[1] = __float2bfloat16(v.y - __bfloat162float(h1));
    l[2] = __float2bfloat16(v.z - __bfloat162float(h2));
    l[3] = __float2bfloat16(v.w - __bfloat162float(h3));
}

__global__ __launch_bounds__(256) void cvt_x_kernel(const float* __restrict__ x)
{
    size_t i = ((size_t)blockIdx.x * 256 + threadIdx.x) * 4;
    float4 v = *(const float4*)(x + i);
    __nv_bfloat16 h[4], l[4];
    split4(v, h, l);
    *(ulonglong1*)(g_xh + i) = *(ulonglong1*)h;
    *(ulonglong1*)(g_xl + i) = *(ulonglong1*)l;
}

__global__ __launch_bounds__(256) void cvt_ao_kernel()
{
    size_t i = ((size_t)blockIdx.x * 256 + threadIdx.x) * 4;
    float4 v = *(const float4*)(g_ao + i);
    __nv_bfloat16 h[4], l[4];
    split4(v, h, l);
    *(ulonglong1*)(g_aoh + i) = *(ulonglong1*)h;
    *(ulonglong1*)(g_aol + i) = *(ulonglong1*)l;
}

// ---------------- weight transpose + split: W[K,N] -> Wt hi/lo [N,K] (qp,kp,v,o) ----------------
__global__ __launch_bounds__(256) void wtrans_kernel(
    const float* __restrict__ Wqp, const float* __restrict__ Wkp,
    const float* __restrict__ Wv,  const float* __restrict__ Wo)
{
    __shared__ float tile[32][33];
    const float* W;
    switch (blockIdx.z) {
        case 0: W = Wqp; break;
        case 1: W = Wkp; break;
        case 2: W = Wv;  break;
        default: W = Wo; break;
    }
    int k0 = blockIdx.y * 32, n0 = blockIdx.x * 32;
    int tx = threadIdx.x & 31, ty = threadIdx.x >> 5;
#pragma unroll
    for (int i = 0; i < 4; i++)
        tile[ty + 8 * i][tx] = W[(size_t)(k0 + ty + 8 * i) * 1024 + n0 + tx];
    __syncthreads();
    __nv_bfloat16* th = g_wt2h + (size_t)blockIdx.z * 1048576;
    __nv_bfloat16* tl = g_wt2l + (size_t)blockIdx.z * 1048576;
#pragma unroll
    for (int i = 0; i < 4; i++) {
        int n = n0 + ty + 8 * i, k = k0 + tx;
        float v = tile[tx][ty + 8 * i];
        __nv_bfloat16 h = __float2bfloat16(v);
        th[(size_t)n * 1024 + k] = h;
        tl[(size_t)n * 1024 + k] = __float2bfloat16(v - __bfloat162float(h));
    }
}

// ---------------- wave normalization ----------------
__global__ __launch_bounds__(256) void wave_kernel()
{
    int gid  = blockIdx.x * 8 + (threadIdx.x >> 5);
    int lane = threadIdx.x & 31;
    int qk = gid >> 16;
    int r  = gid & 0xFFFF;
    int h = r & 15;
    int t = (r >> 4) & 2047;
    int b = r >> 15;

    const float* fb = g_wave + (size_t)qk * SLICE;
    const float* pb = g_wave + (size_t)(2 + qk) * SLICE;
    size_t base = ((size_t)(b * T_SEQ + t)) * DMODEL + h * NWAVE;
    float tf = (float)t;

    float f0 = fb[base + lane],      f1 = fb[base + lane + 32];
    float p0 = pb[base + lane],      p1 = pb[base + lane + 32];
    float w0 = sinf(__fadd_rn(__fmul_rn(f0, tf), p0));
    float w1 = sinf(__fadd_rn(__fmul_rn(f1, tf), p1));

    float s = w0 * w0 + w1 * w1;
#pragma unroll
    for (int o = 16; o > 0; o >>= 1) s += __shfl_xor_sync(0xffffffffu, s, o);
    float inv = 1.f / fmaxf(sqrtf(s), 1e-12f);

    float* dst = qk ? g_kn : g_qn;
    size_t ob = ((size_t)((b * HEADS + h) * T_SEQ + t)) * NWAVE;
    dst[ob + lane]      = w0 * inv;
    dst[ob + lane + 32] = w1 * inv;
}

// ---------------- pass 1: per-chunk KV sums ----------------
__global__ __launch_bounds__(256) void kvchunk_kernel()
{
    int c = blockIdx.x, bh = blockIdx.y;
    int b = bh >> 4, h = bh & 15;
    __shared__ float ks[CHUNK * NWAVE];
    __shared__ float vs[CHUNK * HDIM];
    const float* knp = g_kn + ((size_t)bh * T_SEQ + c * CHUNK) * NWAVE;
    const float* vp  = g_v + ((size_t)(b * T_SEQ + c * CHUNK)) * DMODEL + h * HDIM;
    for (int idx = threadIdx.x; idx < CHUNK * NWAVE; idx += 256) {
        ks[idx] = knp[idx];
        int s = idx >> 6, d = idx & 63;
        vs[idx] = vp[(size_t)s * DMODEL + d];
    }
    __syncthreads();
    int tw = (threadIdx.x >> 4) * 4, td = (threadIdx.x & 15) * 4;
    float acc[4][4] = {};
    for (int s = 0; s < CHUNK; s++) {
        float kr[4], vr[4];
#pragma unroll
        for (int i = 0; i < 4; i++) kr[i] = ks[s * NWAVE + tw + i];
#pragma unroll
        for (int j = 0; j < 4; j++) vr[j] = vs[s * HDIM + td + j];
#pragma unroll
        for (int i = 0; i < 4; i++)
#pragma unroll
            for (int j = 0; j < 4; j++)
                acc[i][j] = fmaf(kr[i], vr[j], acc[i][j]);
    }
    float* Mp = g_M + ((size_t)bh * NCHUNK + c) * (NWAVE * HDIM);
#pragma unroll
    for (int i = 0; i < 4; i++)
#pragma unroll
        for (int j = 0; j < 4; j++)
            Mp[(tw + i) * HDIM + td + j] = acc[i][j];
}

// ---------------- pass 2: exclusive prefix sum over chunks ----------------
__global__ __launch_bounds__(256) void prefix_kernel()
{
    int bh = blockIdx.y;
    int e = blockIdx.x * 256 + threadIdx.x;
    size_t base = (size_t)bh * NCHUNK * (NWAVE * HDIM) + e;
    float run = 0.f;
#pragma unroll
    for (int c = 0; c < NCHUNK; c++) {
        g_S[base + (size_t)c * (NWAVE * HDIM)] = run;
        run += g_M[base + (size_t)c * (NWAVE * HDIM)];
    }
}

// ---------------- pass 3: per-chunk output ----------------
__global__ __launch_bounds__(256) void attnout_kernel(const float* __restrict__ scale)
{
    int c = blockIdx.x, bh = blockIdx.y;
    int b = bh >> 4, h = bh & 15;
    int t0 = c * CHUNK;
    __shared__ float Xs[NWAVE * CHUNK];
    __shared__ float Ys[NWAVE * CHUNK];
    __shared__ float Zs[CHUNK * CHUNK];

    const float* qp_ = g_qn + ((size_t)bh * T_SEQ + t0) * NWAVE;
    const float* kp_ = g_kn + ((size_t)bh * T_SEQ + t0) * NWAVE;
    for (int idx = threadIdx.x; idx < CHUNK * NWAVE; idx += 256) {
        int t = idx >> 6, w = idx & 63;
        Xs[w * CHUNK + t] = qp_[idx];
        Ys[w * CHUNK + t] = kp_[idx];
    }
    __syncthreads();

    int ty = threadIdx.x >> 4, tx = threadIdx.x & 15;
    int tr = ty * 4, sc = tx * 4;

    {
        float acc[4][4] = {};
        for (int w = 0; w < NWAVE; w++) {
            float qr[4], kr[4];
#pragma unroll
            for (int i = 0; i < 4; i++) qr[i] = Xs[w * CHUNK + tr + i];
#pragma unroll
            for (int j = 0; j < 4; j++) kr[j] = Ys[w * CHUNK + sc + j];
#pragma unroll
            for (int i = 0; i < 4; i++)
#pragma unroll
                for (int j = 0; j < 4; j++)
                    acc[i][j] = fmaf(qr[i], kr[j], acc[i][j]);
        }
#pragma unroll
        for (int i = 0; i < 4; i++)
#pragma unroll
            for (int j = 0; j < 4; j++)
                Zs[(tr + i) * CHUNK + sc + j] = (sc + j <= tr + i) ? acc[i][j] : 0.f;
    }
    __syncthreads();

    const float* vp = g_v + ((size_t)(b * T_SEQ + t0)) * DMODEL + h * HDIM;
    for (int idx = threadIdx.x; idx < CHUNK * HDIM; idx += 256) {
        int s = idx >> 6, d = idx & 63;
        Ys[idx] = vp[(size_t)s * DMODEL + d];
    }
    __syncthreads();

    float out[4][4] = {};
    for (int s = 0; s < CHUNK; s++) {
        float ar[4], vr[4];
#pragma unroll
        for (int i = 0; i < 4; i++) ar[i] = Zs[(tr + i) * CHUNK + s];
#pragma unroll
        for (int j = 0; j < 4; j++) vr[j] = Ys[s * HDIM + sc + j];
#pragma unroll
        for (int i = 0; i < 4; i++)
#pragma unroll
            for (int j = 0; j < 4; j++)
                out[i][j] = fmaf(ar[i], vr[j], out[i][j]);
    }
    __syncthreads();

    const float* Sp = g_S + ((size_t)bh * NCHUNK + c) * (NWAVE * HDIM);
    for (int idx = threadIdx.x; idx < NWAVE * HDIM; idx += 256) Ys[idx] = Sp[idx];
    __syncthreads();

    for (int w = 0; w < NWAVE; w++) {
        float qr[4], sr[4];
#pragma unroll
        for (int i = 0; i < 4; i++) qr[i] = Xs[w * CHUNK + tr + i];
#pragma unroll
        for (int j = 0; j < 4; j++) sr[j] = Ys[w * HDIM + sc + j];
#pragma unroll
        for (int i = 0; i < 4; i++)
#pragma unroll
            for (int j = 0; j < 4; j++)
                out[i][j] = fmaf(qr[i], sr[j], out[i][j]);
    }

    float sch = scale[h];
    float* op = g_ao + ((size_t)(b * T_SEQ + t0)) * DMODEL + h * HDIM;
#pragma unroll
    for (int i = 0; i < 4; i++) {
        float fac = sch / sqrtf((float)(t0 + tr + i + 1));
        float4 o;
        o.x = out[i][0] * fac;
        o.y = out[i][1] * fac;
        o.z = out[i][2] * fac;
        o.w = out[i][3] * fac;
        *(float4*)(op + (size_t)(tr + i) * DMODEL + sc) = o;
    }
}

// ---------------- launch ----------------
extern "C" void kernel_launch(void* const* d_in, const int* in_sizes, int n_in,
                              void* d_out, int out_size)
{
    const float* x   = (const float*)d_in[0];
    const float* Wqf = (const float*)d_in[1];
    const float* bqf = (const float*)d_in[2];
    const float* Wkf = (const float*)d_in[3];
    const float* bkf = (const float*)d_in[4];
    const float* Wqp = (const float*)d_in[5];
    const float* bqp = (const float*)d_in[6];
    const float* Wkp = (const float*)d_in[7];
    const float* bkp = (const float*)d_in[8];
    const float* Wv  = (const float*)d_in[9];
    const float* bv  = (const float*)d_in[10];
    const float* Wo  = (const float*)d_in[11];
    const float* bo  = (const float*)d_in[12];
    const float* scl = (const float*)d_in[13];

    cudaFuncSetAttribute(proj_all, cudaFuncAttributeMaxDynamicSharedMemorySize, GEMM_DSMEM);
    cudaFuncSetAttribute(out_tc,   cudaFuncAttributeMaxDynamicSharedMemorySize, GEMM_DSMEM);

    cvt_x_kernel<<<SLICE / 1024, 256>>>(x);
    wtrans_kernel<<<dim3(32, 32, 4), 256>>>(Wqp, Wkp, Wv, Wo);
    proj_all<<<1280, 256, GEMM_DSMEM>>>(x, Wqf, bqf, Wkf, bkf, bqp, bkp, bv);
    wave_kernel<<<(2 * BATCH * T_SEQ * HEADS) / 8, 256>>>();
    kvchunk_kernel<<<dim3(NCHUNK, BH), 256>>>();
    prefix_kernel<<<dim3(16, BH), 256>>>();
    attnout_kernel<<<dim3(NCHUNK, BH), 256>>>(scl);
    cvt_ao_kernel<<<SLICE / 1024, 256>>>();
    out_tc<<<dim3(8, 32), 256, GEMM_DSMEM>>>(bo, (float*)d_out);
}